// round 14
// baseline (speedup 1.0000x reference)
#include <cuda_runtime.h>
#include <math.h>
#include <stdint.h>

#define B_SZ    32
#define L_SZ    2048
#define NROWS   (B_SZ*L_SZ)      /* 65536 */
#define DMODEL  256
#define DINNER  512
#define NH      8
#define HD      64
#define DSTATE  64
#define CHUNK   64
#define NC      (L_SZ/CHUNK)     /* 32 */
#define CONVD   640
#define DPROJ   1160
#define DFFN    1024

/* ------------------------------------------------------------------ */
__device__ float g_zxbcdt[(size_t)NROWS*DPROJ];
__device__ float g_xbc[(size_t)NROWS*CONVD];
__device__ float g_dtsp[(size_t)NROWS*NH];
__device__ float g_acs[(size_t)B_SZ*NH*L_SZ];
__device__ float g_cdec[B_SZ*NH*NC];
__device__ float g_G[(size_t)B_SZ*NC*CHUNK*CHUNK];
__device__ float g_states[(size_t)B_SZ*NC*NH*HD*DSTATE];  /* [n][p] */
__device__ float g_prev[(size_t)B_SZ*NC*NH*HD*DSTATE];    /* [n][p] */
__device__ float g_yn[(size_t)NROWS*DINNER];              /* unnormalized u */
__device__ float g_scale[(size_t)NROWS];
__device__ float g_t256[(size_t)NROWS*DMODEL];
__device__ float g_hidden[(size_t)NROWS*DMODEL];
__device__ float g_h1[(size_t)NROWS*DFFN];

#define W_IN_OFF   0
#define W_OUT_OFF  (DPROJ*DMODEL)
#define W_FC1_OFF  (W_OUT_OFF + DMODEL*DINNER)
#define W_FC2_OFF  (W_FC1_OFF + DFFN*DMODEL)
#define W_TOTAL    (W_FC2_OFF + DMODEL*DFFN)
__device__ float g_wtf[W_TOTAL];

__device__ __forceinline__ uint32_t f2tf32(float v) {
    uint32_t r;
    asm("cvt.rna.tf32.f32 %0, %1;" : "=r"(r) : "f"(v));
    return r;
}
__device__ __forceinline__ float tf32r(float v) {
    return __uint_as_float(f2tf32(v));
}

__global__ void cvt_tf32(const float* __restrict__ src, float* __restrict__ dst, int n)
{
    int i = blockIdx.x * blockDim.x + threadIdx.x;
    if (i < n) dst[i] = tf32r(src[i]);
}

/* out_w conversion with norm_w folded in */
__global__ void cvt_tf32_nw(const float* __restrict__ src, const float* __restrict__ nw,
                            float* __restrict__ dst, int n)
{
    int i = blockIdx.x * blockDim.x + threadIdx.x;
    if (i < n) dst[i] = tf32r(src[i] * nw[i & (DINNER - 1)]);
}

/* ------------------------------------------------------------------ */
__device__ __forceinline__ void mma_tf32(float c[4],
    uint32_t a0, uint32_t a1, uint32_t a2, uint32_t a3,
    uint32_t b0, uint32_t b1)
{
    asm volatile(
        "mma.sync.aligned.m16n8k8.row.col.f32.tf32.tf32.f32 "
        "{%0,%1,%2,%3}, {%4,%5,%6,%7}, {%8,%9}, {%0,%1,%2,%3};"
        : "+f"(c[0]), "+f"(c[1]), "+f"(c[2]), "+f"(c[3])
        : "r"(a0), "r"(a1), "r"(a2), "r"(a3), "r"(b0), "r"(b1));
}

/* ------------------------------------------------------------------ */
/* tf32 tensor-core GEMM, 3-stage cp.async pipeline                    */
/* ------------------------------------------------------------------ */
#define SROW 36
#define TBUF (128*SROW)

__device__ __forceinline__ void cpa16(uint32_t sdst, const float* gsrc) {
    asm volatile("cp.async.cg.shared.global [%0], [%1], 16;"
                 :: "r"(sdst), "l"(gsrc));
}
__device__ __forceinline__ void cpa16z(uint32_t sdst, const float* gsrc, int valid) {
    int sz = valid ? 16 : 0;
    asm volatile("cp.async.cg.shared.global [%0], [%1], 16, %2;"
                 :: "r"(sdst), "l"(gsrc), "r"(sz));
}

__global__ void __launch_bounds__(128, 2)
gemm_tf32(const float* __restrict__ A, const float* __restrict__ W,
          const float* __restrict__ bias, float* __restrict__ C,
          const float* __restrict__ rowscale,
          int M, int N, int K, int act, int cvtA)
{
    extern __shared__ float sm[];
    float* As = sm;
    float* Ws = sm + 3 * TBUF;
    uint32_t sAs = (uint32_t)__cvta_generic_to_shared(As);
    uint32_t sWs = (uint32_t)__cvta_generic_to_shared(Ws);

    int tid  = threadIdx.x;
    int warp = tid >> 5, lane = tid & 31;
    int wm = (warp >> 1) * 64;
    int wn = (warp & 1) * 64;
    int m0 = blockIdx.y * 128;
    int n0 = blockIdx.x * 128;
    int g  = lane >> 2;
    int tg = lane & 3;

    float acc[4][8][4];
#pragma unroll
    for (int i = 0; i < 4; i++)
#pragma unroll
        for (int j = 0; j < 8; j++)
#pragma unroll
            for (int r = 0; r < 4; r++) acc[i][j][r] = 0.f;

    int ntiles = K >> 5;

#define FILL(BUF, K0) do {                                                   \
    int _k0 = (K0);                                                          \
    _Pragma("unroll")                                                        \
    for (int i = 0; i < 8; i++) {                                            \
        int c = tid + i * 128;                                               \
        int row = c >> 3, cc = (c & 7) * 4;                                  \
        cpa16(sAs + (((BUF)*TBUF + row*SROW + cc) << 2),                     \
              A + (size_t)(m0 + row) * K + _k0 + cc);                        \
        int wr = n0 + row;                                                   \
        int wv = wr < N;                                                     \
        cpa16z(sWs + (((BUF)*TBUF + row*SROW + cc) << 2),                    \
               W + (size_t)(wv ? wr : 0) * K + _k0 + cc, wv);                \
    }                                                                        \
    asm volatile("cp.async.commit_group;");                                  \
} while (0)

    FILL(0, 0);
    if (ntiles > 1) FILL(1, 32);
    for (int kt = 0; kt < ntiles; kt++) {
        if (kt + 2 < ntiles) {
            FILL((kt + 2) % 3, (kt + 2) * 32);
            asm volatile("cp.async.wait_group 2;");
        } else if (kt + 1 < ntiles) {
            asm volatile("cp.async.wait_group 1;");
        } else {
            asm volatile("cp.async.wait_group 0;");
        }
        __syncthreads();

        int buf = kt % 3;
        const uint32_t* Ab = (const uint32_t*)(As + buf * TBUF);
        const uint32_t* Wb = (const uint32_t*)(Ws + buf * TBUF);
#pragma unroll
        for (int ks = 0; ks < 4; ks++) {
            int k0 = ks * 8;
            uint32_t af[4][4];
#pragma unroll
            for (int mt = 0; mt < 4; mt++) {
                const uint32_t* ap = Ab + (wm + mt * 16 + g) * SROW + k0 + tg;
                af[mt][0] = ap[0];
                af[mt][1] = ap[8 * SROW];
                af[mt][2] = ap[4];
                af[mt][3] = ap[8 * SROW + 4];
            }
            if (cvtA) {
#pragma unroll
                for (int mt = 0; mt < 4; mt++)
#pragma unroll
                    for (int i = 0; i < 4; i++)
                        af[mt][i] = f2tf32(__uint_as_float(af[mt][i]));
            }
            uint32_t bf[8][2];
#pragma unroll
            for (int nt = 0; nt < 8; nt++) {
                const uint32_t* bp = Wb + (wn + nt * 8 + g) * SROW + k0 + tg;
                bf[nt][0] = bp[0];
                bf[nt][1] = bp[4];
            }
#pragma unroll
            for (int mt = 0; mt < 4; mt++)
#pragma unroll
                for (int nt = 0; nt < 8; nt++)
                    mma_tf32(acc[mt][nt], af[mt][0], af[mt][1], af[mt][2],
                             af[mt][3], bf[nt][0], bf[nt][1]);
        }
        __syncthreads();
    }

#pragma unroll
    for (int mt = 0; mt < 4; mt++) {
        int r0 = m0 + wm + mt * 16 + g;
        float s0 = rowscale ? rowscale[r0]     : 1.f;
        float s2 = rowscale ? rowscale[r0 + 8] : 1.f;
#pragma unroll
        for (int nt = 0; nt < 8; nt++) {
            int col = n0 + wn + nt * 8 + 2 * tg;
            if (col + 1 < N) {
                float b0 = bias[col], b1 = bias[col + 1];
                float v0 = acc[mt][nt][0] * s0 + b0;
                float v1 = acc[mt][nt][1] * s0 + b1;
                float v2 = acc[mt][nt][2] * s2 + b0;
                float v3 = acc[mt][nt][3] * s2 + b1;
                if (act == 1) {
                    float t;
                    t = fminf(fmaxf(v0 + 3.f, 0.f), 6.f); v0 = tf32r(v0 * t * (1.f/6.f));
                    t = fminf(fmaxf(v1 + 3.f, 0.f), 6.f); v1 = tf32r(v1 * t * (1.f/6.f));
                    t = fminf(fmaxf(v2 + 3.f, 0.f), 6.f); v2 = tf32r(v2 * t * (1.f/6.f));
                    t = fminf(fmaxf(v3 + 3.f, 0.f), 6.f); v3 = tf32r(v3 * t * (1.f/6.f));
                }
                *(float2*)(C + (size_t)r0 * N + col)       = make_float2(v0, v1);
                *(float2*)(C + (size_t)(r0 + 8) * N + col) = make_float2(v2, v3);
            } else if (col < N) {
                float b0 = bias[col];
                float v0 = acc[mt][nt][0] * s0 + b0;
                float v2 = acc[mt][nt][2] * s2 + b0;
                if (act == 1) {
                    float t;
                    t = fminf(fmaxf(v0 + 3.f, 0.f), 6.f); v0 = tf32r(v0 * t * (1.f/6.f));
                    t = fminf(fmaxf(v2 + 3.f, 0.f), 6.f); v2 = tf32r(v2 * t * (1.f/6.f));
                }
                C[(size_t)r0 * N + col]       = v0;
                C[(size_t)(r0 + 8) * N + col] = v2;
            }
        }
    }
}

/* ------------------------------------------------------------------ */
/* Causal conv (K=4) + SiLU, smem-tiled                                */
/* ------------------------------------------------------------------ */
#define CCH 160
__global__ void __launch_bounds__(320)
conv_kernel(const float* __restrict__ w, const float* __restrict__ cb)
{
    __shared__ float sc[67 * CCH];
    int bc = blockIdx.x;
    int ct = blockIdx.y;
    int b = bc / NC, c = bc % NC;
    int l0 = c * 64;
    int ch0 = ct * CCH;
    int tid = threadIdx.x;

    for (int i = tid; i < 67 * (CCH/4); i += 320) {
        int r = i / (CCH/4), c4 = (i % (CCH/4)) * 4;
        int ls = l0 - 3 + r;
        float4 v = make_float4(0.f, 0.f, 0.f, 0.f);
        if (ls >= 0)
            v = *(const float4*)(g_zxbcdt +
                (size_t)(b * L_SZ + ls) * DPROJ + DINNER + ch0 + c4);
        *(float4*)&sc[r * CCH + c4] = v;
    }
    __syncthreads();

    int cg = tid % 40;
    int lb = tid / 40;
    int ch = ch0 + cg * 4;
    float wr[4][4];
#pragma unroll
    for (int j = 0; j < 4; j++)
#pragma unroll
        for (int k = 0; k < 4; k++)
            wr[j][k] = __ldg(&w[(ch + j) * 4 + k]);
    float4 cbv = *(const float4*)(cb + ch);

#pragma unroll
    for (int pass = 0; pass < 8; pass++) {
        int l = lb + pass * 8;
        float4 acc = cbv;
#pragma unroll
        for (int k = 0; k < 4; k++) {
            float4 xv = *(float4*)&sc[(l + k) * CCH + cg * 4];
            acc.x += xv.x * wr[0][k];
            acc.y += xv.y * wr[1][k];
            acc.z += xv.z * wr[2][k];
            acc.w += xv.w * wr[3][k];
        }
        acc.x = acc.x / (1.f + __expf(-acc.x));
        acc.y = acc.y / (1.f + __expf(-acc.y));
        acc.z = acc.z / (1.f + __expf(-acc.z));
        acc.w = acc.w / (1.f + __expf(-acc.w));
        *(float4*)(g_xbc + (size_t)(b * L_SZ + l0 + l) * CONVD + ch) = acc;
    }
}

__global__ void dtsp_kernel(const float* __restrict__ dtb)
{
    int idx = blockIdx.x * blockDim.x + threadIdx.x;
    if (idx >= NROWS * NH) return;
    int h = idx & 7;
    int r = idx >> 3;
    float v = g_zxbcdt[(size_t)r * DPROJ + (DPROJ - NH) + h] + dtb[h];
    g_dtsp[idx] = (v > 20.f) ? v : log1pf(__expf(v));
}

__global__ void acs_kernel(const float* __restrict__ A_log)
{
    __shared__ float sh[64];
    int id = blockIdx.x;
    int c  = id % NC;
    int bh = id / NC;
    int h  = bh % NH;
    int b  = bh / NH;
    int l  = threadIdx.x;
    float Ah = -expf(A_log[h]);
    sh[l] = g_dtsp[(size_t)(b * L_SZ + c * 64 + l) * NH + h] * Ah;
    __syncthreads();
    for (int off = 1; off < 64; off <<= 1) {
        float v = (l >= off) ? sh[l - off] : 0.f;
        __syncthreads();
        sh[l] += v;
        __syncthreads();
    }
    g_acs[(size_t)id * 64 + l] = sh[l];
    if (l == 63) g_cdec[id] = __expf(sh[63]);
}

/* ------------------------------------------------------------------ */
#define SR 68
#define SZT (64*SR)

__device__ __forceinline__ void mm64(const float* __restrict__ sA,
                                     const float* __restrict__ sB,
                                     int wm, int wn, int g, int tg,
                                     float acc[4][4])
{
#pragma unroll
    for (int k0 = 0; k0 < 64; k0 += 8) {
        uint32_t a0 = f2tf32(sA[(wm + g)     * SR + k0 + tg]);
        uint32_t a1 = f2tf32(sA[(wm + 8 + g) * SR + k0 + tg]);
        uint32_t a2 = f2tf32(sA[(wm + g)     * SR + k0 + 4 + tg]);
        uint32_t a3 = f2tf32(sA[(wm + 8 + g) * SR + k0 + 4 + tg]);
#pragma unroll
        for (int nt = 0; nt < 4; nt++) {
            uint32_t b0 = f2tf32(sB[(wn + nt * 8 + g) * SR + k0 + tg]);
            uint32_t b1 = f2tf32(sB[(wn + nt * 8 + g) * SR + k0 + 4 + tg]);
            mma_tf32(acc[nt], a0, a1, a2, a3, b0, b1);
        }
    }
}

/* ------------------------------------------------------------------ */
/* Chunk kernel: G = C·B^T -> g_G ; states per head -> g_states        */
/* ------------------------------------------------------------------ */
extern __shared__ float smem[];
__global__ void __launch_bounds__(256, 3)
chunk_kernel(void)
{
    float* sB   = smem;
    float* sBt  = smem + SZT;
    float* sC   = smem + 2*SZT;
    float* sXdt = smem + 3*SZT;
    float* sDec = smem + 4*SZT;
    float* sDt  = smem + 4*SZT + 64;

    int bc = blockIdx.x;
    int b = bc / NC, c = bc % NC;
    int tid = threadIdx.x;
    int base = b * L_SZ + c * CHUNK;

    int warp = tid >> 5, lane = tid & 31;
    int g  = lane >> 2, tg = lane & 3;
    int wm = (warp >> 1) * 16;
    int wn = (warp & 1) * 32;

    for (int i = tid; i < 1024; i += 256) {
        int l = i >> 4, n4 = (i & 15) * 4;
        const float* row = g_xbc + (size_t)(base + l) * CONVD + DINNER;
        float4 bv = *(const float4*)(row + n4);
        float4 cv = *(const float4*)(row + DSTATE + n4);
        *(float4*)&sB[l * SR + n4] = bv;
        *(float4*)&sC[l * SR + n4] = cv;
        sBt[(n4 + 0) * SR + l] = bv.x;
        sBt[(n4 + 1) * SR + l] = bv.y;
        sBt[(n4 + 2) * SR + l] = bv.z;
        sBt[(n4 + 3) * SR + l] = bv.w;
    }
    __syncthreads();

    {
        float acc[4][4];
#pragma unroll
        for (int i = 0; i < 4; i++)
#pragma unroll
            for (int j = 0; j < 4; j++) acc[i][j] = 0.f;
        mm64(sC, sB, wm, wn, g, tg, acc);
        float* gp = g_G + (size_t)bc * 4096;
#pragma unroll
        for (int nt = 0; nt < 4; nt++) {
            int cl = wn + nt * 8 + 2 * tg;
            *(float2*)(gp + (wm + g)     * 64 + cl) = make_float2(acc[nt][0], acc[nt][1]);
            *(float2*)(gp + (wm + 8 + g) * 64 + cl) = make_float2(acc[nt][2], acc[nt][3]);
        }
    }

    for (int h = 0; h < NH; h++) {
        __syncthreads();
        if (tid < 64) {
            sDt[tid] = g_dtsp[(size_t)(base + tid) * NH + h];
            const float* ac = g_acs + ((size_t)(b * NH + h) * NC + c) * 64;
            sDec[tid] = __expf(ac[63] - ac[tid]);
        }
        __syncthreads();

        for (int i = tid; i < 1024; i += 256) {
            int s = i >> 4, p4 = (i & 15) * 4;
            float4 xv = *(const float4*)(g_xbc + (size_t)(base + s) * CONVD + h * HD + p4);
            float sc = sDt[s] * sDec[s];
            sXdt[(p4 + 0) * SR + s] = xv.x * sc;
            sXdt[(p4 + 1) * SR + s] = xv.y * sc;
            sXdt[(p4 + 2) * SR + s] = xv.z * sc;
            sXdt[(p4 + 3) * SR + s] = xv.w * sc;
        }
        __syncthreads();

        float acc[4][4];
#pragma unroll
        for (int i = 0; i < 4; i++)
#pragma unroll
            for (int j = 0; j < 4; j++) acc[i][j] = 0.f;
        mm64(sBt, sXdt, wm, wn, g, tg, acc);
        float* sp = g_states + (((size_t)bc * NH + h) << 12);
#pragma unroll
        for (int nt = 0; nt < 4; nt++) {
            int p = wn + nt * 8 + 2 * tg;
            *(float2*)(sp + (wm + g)     * 64 + p) = make_float2(acc[nt][0], acc[nt][1]);
            *(float2*)(sp + (wm + 8 + g) * 64 + p) = make_float2(acc[nt][2], acc[nt][3]);
        }
    }
}

/* sequential inter-chunk state recurrence                              */
__global__ void scan_kernel(void)
{
    int idx = blockIdx.x * blockDim.x + threadIdx.x;
    int e = idx & 4095;
    int h = (idx >> 12) & 7;
    int b = idx >> 15;
    float carry = 0.f;
    for (int c = 0; c < NC; c++) {
        size_t off = (((size_t)(b * NC + c) * NH + h) << 12) + e;
        g_prev[off] = carry;
        carry = carry * g_cdec[(b * NH + h) * NC + c] + g_states[off];
    }
}

/* ------------------------------------------------------------------ */
/* ssd_y: Y = M·X + E·(C·prev^T) + Dp·X, gated by silu(z).            */
/* Banded exp factorization: exp(acs_l-acs_s) =                        */
/*   exp(acs_l-acs_{l0}) * exp(acs_{l0}-acs_s), l0 = 8-row band start. */
/* dt[s] folded into band factor.                                      */
/* ------------------------------------------------------------------ */
__global__ void __launch_bounds__(256, 3)
ssd_y(const float* __restrict__ Dp)
{
    float* sC    = smem;
    float* sG    = smem + SZT;
    float* sT    = smem + 2*SZT;
    float* sXt   = smem + 3*SZT;
    float* sE    = smem + 4*SZT;
    float* sAcs  = smem + 4*SZT + 64;
    float* sSS   = smem + 4*SZT + 128;
    float* sRow  = smem + 4*SZT + 192;          /* 64 */
    float* sBand = smem + 4*SZT + 256;          /* 8 x 64 */

    int bc = blockIdx.x;
    int b = bc / NC, c = bc % NC;
    int tid = threadIdx.x;
    int base = b * L_SZ + c * CHUNK;

    int warp = tid >> 5, lane = tid & 31;
    int g  = lane >> 2, tg = lane & 3;
    int wm = (warp >> 1) * 16;
    int wn = (warp & 1) * 32;
    int r0 = wm + g, r1 = wm + 8 + g;

    const float* gp = g_G + (size_t)bc * 4096;
    for (int i = tid; i < 1024; i += 256) {
        int l = i >> 4, n4 = (i & 15) * 4;
        *(float4*)&sC[l * SR + n4] =
            *(const float4*)(g_xbc + (size_t)(base + l) * CONVD + DINNER + DSTATE + n4);
        *(float4*)&sG[l * SR + n4] = *(const float4*)(gp + l * 64 + n4);
    }
    if (tid < 64) sSS[tid] = 0.f;
    __syncthreads();

    float ss0 = 0.f, ss1 = 0.f;

    for (int h = 0; h < NH; h++) {
        if (tid < 64) {
            const float* ac = g_acs + ((size_t)(b * NH + h) * NC + c) * 64;
            float a = ac[tid];
            sAcs[tid] = a;
            sE[tid]   = __expf(a);
            /* row factor: exp(acs_l - acs_{band start}) */
            sRow[tid] = __expf(a - ac[tid & ~7]);
        }
        __syncthreads();
        /* band factors: sBand[bd][s] = exp(acs_{bd*8} - acs_s) * dt[s]
           (only entries with s <= bd*8+7 are ever consumed)            */
        for (int i = tid; i < 512; i += 256) {
            int bd = i >> 6, s = i & 63;
            float v = 0.f;
            if (s <= bd * 8 + 7)
                v = __expf(sAcs[bd * 8] - sAcs[s]) *
                    g_dtsp[(size_t)(base + s) * NH + h];
            sBand[i] = v;
        }
        __syncthreads();

        /* M[l][s] = G * rowfac[l] * bandfac[l>>3][s], masked */
        for (int i = tid; i < 4096; i += 256) {
            int l = i >> 6, s = i & 63;
            sT[l * SR + s] = (s <= l)
                ? sG[l * SR + s] * sRow[l] * sBand[((l >> 3) << 6) + s] : 0.f;
        }
        /* Xt[p][s] = RAW X[s][p] */
        for (int i = tid; i < 1024; i += 256) {
            int s = i >> 4, p4 = (i & 15) * 4;
            float4 xv = *(const float4*)(g_xbc + (size_t)(base + s) * CONVD + h * HD + p4);
            sXt[(p4 + 0) * SR + s] = xv.x;
            sXt[(p4 + 1) * SR + s] = xv.y;
            sXt[(p4 + 2) * SR + s] = xv.z;
            sXt[(p4 + 3) * SR + s] = xv.w;
        }
        __syncthreads();

        /* Y_diag = M·X */
        float accY[4][4];
#pragma unroll
        for (int i = 0; i < 4; i++)
#pragma unroll
            for (int j = 0; j < 4; j++) accY[i][j] = 0.f;
        mm64(sT, sXt, wm, wn, g, tg, accY);
        __syncthreads();

        /* prev^T into sT */
        const float* pv = g_prev + (((size_t)bc * NH + h) << 12);
        for (int i = tid; i < 1024; i += 256) {
            int n = i >> 4, p4 = (i & 15) * 4;
            float4 pvv = *(const float4*)(pv + n * 64 + p4);
            sT[(p4 + 0) * SR + n] = pvv.x;
            sT[(p4 + 1) * SR + n] = pvv.y;
            sT[(p4 + 2) * SR + n] = pvv.z;
            sT[(p4 + 3) * SR + n] = pvv.w;
        }
        __syncthreads();

        float accO[4][4];
#pragma unroll
        for (int i = 0; i < 4; i++)
#pragma unroll
            for (int j = 0; j < 4; j++) accO[i][j] = 0.f;
        mm64(sC, sT, wm, wn, g, tg, accO);

        float Dph = __ldg(&Dp[h]);
        float e0 = sE[r0], e1 = sE[r1];
#pragma unroll
        for (int nt = 0; nt < 4; nt++) {
            int p = wn + nt * 8 + 2 * tg;
            float x00 = sXt[(p + 0) * SR + r0];
            float x01 = sXt[(p + 1) * SR + r0];
            float x10 = sXt[(p + 0) * SR + r1];
            float x11 = sXt[(p + 1) * SR + r1];
            float2 z0 = *(const float2*)(g_zxbcdt + (size_t)(base + r0) * DPROJ + h * HD + p);
            float2 z1 = *(const float2*)(g_zxbcdt + (size_t)(base + r1) * DPROJ + h * HD + p);
            float y00 = accY[nt][0] + e0 * accO[nt][0] + Dph * x00;
            float y01 = accY[nt][1] + e0 * accO[nt][1] + Dph * x01;
            float y10 = accY[nt][2] + e1 * accO[nt][2] + Dph * x10;
            float y11 = accY[nt][3] + e1 * accO[nt][3] + Dph * x11;
            float u00 = y00 * (z0.x / (1.f + __expf(-z0.x)));
            float u01 = y01 * (z0.y / (1.f + __expf(-z0.y)));
            float u10 = y10 * (z1.x / (1.f + __expf(-z1.x)));
            float u11 = y11 * (z1.y / (1.f + __expf(-z1.y)));
            ss0 += u00 * u00 + u01 * u01;
            ss1 += u10 * u10 + u11 * u11;
            *(float2*)(g_yn + (size_t)(base + r0) * DINNER + h * HD + p) =
                make_float2(tf32r(u00), tf32r(u01));
            *(float2*)(g_yn + (size_t)(base + r1) * DINNER + h * HD + p) =
                make_float2(tf32r(u10), tf32r(u11));
        }
        __syncthreads();
    }

    atomicAdd(&sSS[r0], ss0);
    atomicAdd(&sSS[r1], ss1);
    __syncthreads();
    if (tid < 64)
        g_scale[base + tid] = rsqrtf(sSS[tid] / 512.f + 1e-12f);
}

/* LayerNorm(a + res) * g + b  -- warp per row                         */
__global__ void __launch_bounds__(256)
ln_res(const float* __restrict__ a, const float* __restrict__ res,
       const float* __restrict__ g, const float* __restrict__ bb,
       float* __restrict__ out, int rnd)
{
    int row  = blockIdx.x * 8 + (threadIdx.x >> 5);
    int lane = threadIdx.x & 31;
    const float* ar = a   + (size_t)row * 256;
    const float* rr = res + (size_t)row * 256;

    float v[8];
    float s = 0.f;
#pragma unroll
    for (int j = 0; j < 8; j++) {
        int cidx = lane + j * 32;
        v[j] = ar[cidx] + rr[cidx];
        s += v[j];
    }
#pragma unroll
    for (int o = 16; o > 0; o >>= 1) s += __shfl_xor_sync(0xffffffff, s, o);
    float mean = s * (1.f / 256.f);

    float vs = 0.f;
#pragma unroll
    for (int j = 0; j < 8; j++) {
        float d = v[j] - mean;
        vs += d * d;
    }
#pragma unroll
    for (int o = 16; o > 0; o >>= 1) vs += __shfl_xor_sync(0xffffffff, vs, o);
    float inv = rsqrtf(vs * (1.f / 256.f) + 1e-12f);

    float* orow = out + (size_t)row * 256;
#pragma unroll
    for (int j = 0; j < 8; j++) {
        int cidx = lane + j * 32;
        float o = (v[j] - mean) * inv * g[cidx] + bb[cidx];
        orow[cidx] = rnd ? tf32r(o) : o;
    }
}

/* ------------------------------------------------------------------ */
extern "C" void kernel_launch(void* const* d_in, const int* in_sizes, int n_in,
                              void* d_out, int out_size)
{
    const float* x       = (const float*)d_in[0];
    const float* in_w    = (const float*)d_in[1];
    const float* in_b    = (const float*)d_in[2];
    const float* conv_w  = (const float*)d_in[3];
    const float* conv_b  = (const float*)d_in[4];
    const float* dt_bias = (const float*)d_in[5];
    const float* A_log   = (const float*)d_in[6];
    const float* Dp      = (const float*)d_in[7];
    const float* norm_w  = (const float*)d_in[8];
    const float* out_w   = (const float*)d_in[9];
    const float* out_b   = (const float*)d_in[10];
    const float* ln_g    = (const float*)d_in[11];
    const float* ln_b    = (const float*)d_in[12];
    const float* fc1_w   = (const float*)d_in[13];
    const float* fc1_b   = (const float*)d_in[14];
    const float* fc2_w   = (const float*)d_in[15];
    const float* fc2_b   = (const float*)d_in[16];
    const float* fln_g   = (const float*)d_in[17];
    const float* fln_b   = (const float*)d_in[18];
    float* out = (float*)d_out;

    void *p;
    cudaGetSymbolAddress(&p, g_zxbcdt);  float* zx     = (float*)p;
    cudaGetSymbolAddress(&p, g_yn);      float* yn     = (float*)p;
    cudaGetSymbolAddress(&p, g_t256);    float* t256   = (float*)p;
    cudaGetSymbolAddress(&p, g_hidden);  float* hidden = (float*)p;
    cudaGetSymbolAddress(&p, g_h1);      float* h1     = (float*)p;
    cudaGetSymbolAddress(&p, g_wtf);     float* wtf    = (float*)p;
    cudaGetSymbolAddress(&p, g_scale);   float* rscale = (float*)p;

    static int chunk_smem = (4 * SZT + 128) * 4;           /* 70,144 B */
    static int ssdy_smem  = (4 * SZT + 256 + 512 + 64) * 4;/* 72,960 B */
    cudaFuncSetAttribute(chunk_kernel,
                         cudaFuncAttributeMaxDynamicSharedMemorySize, chunk_smem);
    cudaFuncSetAttribute(ssd_y,
                         cudaFuncAttributeMaxDynamicSharedMemorySize, ssdy_smem);
    cudaFuncSetAttribute(gemm_tf32,
                         cudaFuncAttributeMaxDynamicSharedMemorySize, 110592);

    /* 0. weight tf32 conversions (norm_w folded into out_w) */
    cvt_tf32<<<(DPROJ*DMODEL + 255)/256, 256>>>(in_w,  wtf + W_IN_OFF,  DPROJ*DMODEL);
    cvt_tf32_nw<<<(DMODEL*DINNER + 255)/256, 256>>>(out_w, norm_w,
                                                    wtf + W_OUT_OFF, DMODEL*DINNER);
    cvt_tf32<<<(DFFN*DMODEL + 255)/256, 256>>>(fc1_w,  wtf + W_FC1_OFF, DFFN*DMODEL);
    cvt_tf32<<<(DMODEL*DFFN + 255)/256, 256>>>(fc2_w,  wtf + W_FC2_OFF, DMODEL*DFFN);

    /* 1. in_proj (A fragments converted inline) */
    gemm_tf32<<<dim3((DPROJ + 127) / 128, NROWS / 128), 128, 110592>>>(
        x, wtf + W_IN_OFF, in_b, zx, NULL, NROWS, DPROJ, DMODEL, 0, 1);
    /* 2-4 */
    conv_kernel<<<dim3(B_SZ * NC, CONVD / CCH), 320>>>(conv_w, conv_b);
    dtsp_kernel<<<(NROWS * NH + 255) / 256, 256>>>(dt_bias);
    acs_kernel<<<B_SZ * NH * NC, 64>>>(A_log);
    /* 5. intra-chunk */
    chunk_kernel<<<B_SZ * NC, 256, chunk_smem>>>();
    /* 6. inter-chunk scan */
    scan_kernel<<<(B_SZ * NH * HD * DSTATE + 255) / 256, 256>>>();
    /* 7. Y + gate */
    ssd_y<<<B_SZ * NC, 256, ssdy_smem>>>(Dp);
    /* 9. out_proj with deferred RMS row-scale */
    gemm_tf32<<<dim3(DMODEL / 128, NROWS / 128), 128, 110592>>>(
        yn, wtf + W_OUT_OFF, out_b, t256, rscale, NROWS, DMODEL, DINNER, 0, 0);
    /* 10 */
    ln_res<<<NROWS / 8, 256>>>(t256, x, ln_g, ln_b, hidden, 1);
    /* 11 */
    gemm_tf32<<<dim3(DFFN / 128, NROWS / 128), 128, 110592>>>(
        hidden, wtf + W_FC1_OFF, fc1_b, h1, NULL, NROWS, DFFN, DMODEL, 1, 0);
    /* 12 */
    gemm_tf32<<<dim3(DMODEL / 128, NROWS / 128), 128, 110592>>>(
        h1, wtf + W_FC2_OFF, fc2_b, t256, NULL, NROWS, DMODEL, DFFN, 0, 0);
    /* 13 */
    ln_res<<<NROWS / 8, 256>>>(t256, hidden, fln_g, fln_b, out, 0);
}

// round 15
// speedup vs baseline: 1.2258x; 1.2258x over previous
#include <cuda_runtime.h>
#include <math.h>
#include <stdint.h>

#define B_SZ    32
#define L_SZ    2048
#define NROWS   (B_SZ*L_SZ)      /* 65536 */
#define DMODEL  256
#define DINNER  512
#define NH      8
#define HD      64
#define DSTATE  64
#define CHUNK   64
#define NC      (L_SZ/CHUNK)     /* 32 */
#define CONVD   640
#define DPROJ   1160
#define DFFN    1024

/* ------------------------------------------------------------------ */
__device__ float g_zxbcdt[(size_t)NROWS*DPROJ];
__device__ float g_xbc[(size_t)NROWS*CONVD];
__device__ float g_dtsp[(size_t)NROWS*NH];
__device__ float g_acs[(size_t)B_SZ*NH*L_SZ];
__device__ float g_cdec[B_SZ*NH*NC];
__device__ float g_G[(size_t)B_SZ*NC*CHUNK*CHUNK];
__device__ float g_states[(size_t)B_SZ*NC*NH*HD*DSTATE];  /* [n][p] */
__device__ float g_prev[(size_t)B_SZ*NC*NH*HD*DSTATE];    /* [n][p] */
__device__ float g_yn[(size_t)NROWS*DINNER];              /* unnormalized u */
__device__ float g_scale[(size_t)NROWS];
__device__ float g_t256[(size_t)NROWS*DMODEL];
__device__ float g_hidden[(size_t)NROWS*DMODEL];
__device__ float g_h1[(size_t)NROWS*DFFN];

#define W_IN_OFF   0
#define W_OUT_OFF  (DPROJ*DMODEL)
#define W_FC1_OFF  (W_OUT_OFF + DMODEL*DINNER)
#define W_FC2_OFF  (W_FC1_OFF + DFFN*DMODEL)
#define W_TOTAL    (W_FC2_OFF + DMODEL*DFFN)
__device__ float g_wtf[W_TOTAL];

__device__ __forceinline__ uint32_t f2tf32(float v) {
    uint32_t r;
    asm("cvt.rna.tf32.f32 %0, %1;" : "=r"(r) : "f"(v));
    return r;
}
__device__ __forceinline__ float tf32r(float v) {
    return __uint_as_float(f2tf32(v));
}

__global__ void cvt_tf32(const float* __restrict__ src, float* __restrict__ dst, int n)
{
    int i = blockIdx.x * blockDim.x + threadIdx.x;
    if (i < n) dst[i] = tf32r(src[i]);
}

/* out_w conversion with norm_w folded in */
__global__ void cvt_tf32_nw(const float* __restrict__ src, const float* __restrict__ nw,
                            float* __restrict__ dst, int n)
{
    int i = blockIdx.x * blockDim.x + threadIdx.x;
    if (i < n) dst[i] = tf32r(src[i] * nw[i & (DINNER - 1)]);
}

/* ------------------------------------------------------------------ */
__device__ __forceinline__ void mma_tf32(float c[4],
    uint32_t a0, uint32_t a1, uint32_t a2, uint32_t a3,
    uint32_t b0, uint32_t b1)
{
    asm volatile(
        "mma.sync.aligned.m16n8k8.row.col.f32.tf32.tf32.f32 "
        "{%0,%1,%2,%3}, {%4,%5,%6,%7}, {%8,%9}, {%0,%1,%2,%3};"
        : "+f"(c[0]), "+f"(c[1]), "+f"(c[2]), "+f"(c[3])
        : "r"(a0), "r"(a1), "r"(a2), "r"(a3), "r"(b0), "r"(b1));
}

/* ------------------------------------------------------------------ */
/* tf32 tensor-core GEMM, 3-stage cp.async pipeline                    */
/* ------------------------------------------------------------------ */
#define SROW 36
#define TBUF (128*SROW)

__device__ __forceinline__ void cpa16(uint32_t sdst, const float* gsrc) {
    asm volatile("cp.async.cg.shared.global [%0], [%1], 16;"
                 :: "r"(sdst), "l"(gsrc));
}
__device__ __forceinline__ void cpa16z(uint32_t sdst, const float* gsrc, int valid) {
    int sz = valid ? 16 : 0;
    asm volatile("cp.async.cg.shared.global [%0], [%1], 16, %2;"
                 :: "r"(sdst), "l"(gsrc), "r"(sz));
}

__global__ void __launch_bounds__(128, 2)
gemm_tf32(const float* __restrict__ A, const float* __restrict__ W,
          const float* __restrict__ bias, float* __restrict__ C,
          const float* __restrict__ rowscale,
          int M, int N, int K, int act, int cvtA)
{
    extern __shared__ float sm[];
    float* As = sm;
    float* Ws = sm + 3 * TBUF;
    uint32_t sAs = (uint32_t)__cvta_generic_to_shared(As);
    uint32_t sWs = (uint32_t)__cvta_generic_to_shared(Ws);

    int tid  = threadIdx.x;
    int warp = tid >> 5, lane = tid & 31;
    int wm = (warp >> 1) * 64;
    int wn = (warp & 1) * 64;
    int m0 = blockIdx.y * 128;
    int n0 = blockIdx.x * 128;
    int g  = lane >> 2;
    int tg = lane & 3;

    float acc[4][8][4];
#pragma unroll
    for (int i = 0; i < 4; i++)
#pragma unroll
        for (int j = 0; j < 8; j++)
#pragma unroll
            for (int r = 0; r < 4; r++) acc[i][j][r] = 0.f;

    int ntiles = K >> 5;

#define FILL(BUF, K0) do {                                                   \
    int _k0 = (K0);                                                          \
    _Pragma("unroll")                                                        \
    for (int i = 0; i < 8; i++) {                                            \
        int c = tid + i * 128;                                               \
        int row = c >> 3, cc = (c & 7) * 4;                                  \
        cpa16(sAs + (((BUF)*TBUF + row*SROW + cc) << 2),                     \
              A + (size_t)(m0 + row) * K + _k0 + cc);                        \
        int wr = n0 + row;                                                   \
        int wv = wr < N;                                                     \
        cpa16z(sWs + (((BUF)*TBUF + row*SROW + cc) << 2),                    \
               W + (size_t)(wv ? wr : 0) * K + _k0 + cc, wv);                \
    }                                                                        \
    asm volatile("cp.async.commit_group;");                                  \
} while (0)

    FILL(0, 0);
    if (ntiles > 1) FILL(1, 32);
    for (int kt = 0; kt < ntiles; kt++) {
        if (kt + 2 < ntiles) {
            FILL((kt + 2) % 3, (kt + 2) * 32);
            asm volatile("cp.async.wait_group 2;");
        } else if (kt + 1 < ntiles) {
            asm volatile("cp.async.wait_group 1;");
        } else {
            asm volatile("cp.async.wait_group 0;");
        }
        __syncthreads();

        int buf = kt % 3;
        const uint32_t* Ab = (const uint32_t*)(As + buf * TBUF);
        const uint32_t* Wb = (const uint32_t*)(Ws + buf * TBUF);
#pragma unroll
        for (int ks = 0; ks < 4; ks++) {
            int k0 = ks * 8;
            uint32_t af[4][4];
#pragma unroll
            for (int mt = 0; mt < 4; mt++) {
                const uint32_t* ap = Ab + (wm + mt * 16 + g) * SROW + k0 + tg;
                af[mt][0] = ap[0];
                af[mt][1] = ap[8 * SROW];
                af[mt][2] = ap[4];
                af[mt][3] = ap[8 * SROW + 4];
            }
            if (cvtA) {
#pragma unroll
                for (int mt = 0; mt < 4; mt++)
#pragma unroll
                    for (int i = 0; i < 4; i++)
                        af[mt][i] = f2tf32(__uint_as_float(af[mt][i]));
            }
            uint32_t bf[8][2];
#pragma unroll
            for (int nt = 0; nt < 8; nt++) {
                const uint32_t* bp = Wb + (wn + nt * 8 + g) * SROW + k0 + tg;
                bf[nt][0] = bp[0];
                bf[nt][1] = bp[4];
            }
#pragma unroll
            for (int mt = 0; mt < 4; mt++)
#pragma unroll
                for (int nt = 0; nt < 8; nt++)
                    mma_tf32(acc[mt][nt], af[mt][0], af[mt][1], af[mt][2],
                             af[mt][3], bf[nt][0], bf[nt][1]);
        }
        __syncthreads();
    }

#pragma unroll
    for (int mt = 0; mt < 4; mt++) {
        int r0 = m0 + wm + mt * 16 + g;
        float s0 = rowscale ? rowscale[r0]     : 1.f;
        float s2 = rowscale ? rowscale[r0 + 8] : 1.f;
#pragma unroll
        for (int nt = 0; nt < 8; nt++) {
            int col = n0 + wn + nt * 8 + 2 * tg;
            if (col + 1 < N) {
                float b0 = bias[col], b1 = bias[col + 1];
                float v0 = acc[mt][nt][0] * s0 + b0;
                float v1 = acc[mt][nt][1] * s0 + b1;
                float v2 = acc[mt][nt][2] * s2 + b0;
                float v3 = acc[mt][nt][3] * s2 + b1;
                if (act == 1) {
                    float t;
                    t = fminf(fmaxf(v0 + 3.f, 0.f), 6.f); v0 = tf32r(v0 * t * (1.f/6.f));
                    t = fminf(fmaxf(v1 + 3.f, 0.f), 6.f); v1 = tf32r(v1 * t * (1.f/6.f));
                    t = fminf(fmaxf(v2 + 3.f, 0.f), 6.f); v2 = tf32r(v2 * t * (1.f/6.f));
                    t = fminf(fmaxf(v3 + 3.f, 0.f), 6.f); v3 = tf32r(v3 * t * (1.f/6.f));
                }
                *(float2*)(C + (size_t)r0 * N + col)       = make_float2(v0, v1);
                *(float2*)(C + (size_t)(r0 + 8) * N + col) = make_float2(v2, v3);
            } else if (col < N) {
                float b0 = bias[col];
                float v0 = acc[mt][nt][0] * s0 + b0;
                float v2 = acc[mt][nt][2] * s2 + b0;
                if (act == 1) {
                    float t;
                    t = fminf(fmaxf(v0 + 3.f, 0.f), 6.f); v0 = tf32r(v0 * t * (1.f/6.f));
                    t = fminf(fmaxf(v2 + 3.f, 0.f), 6.f); v2 = tf32r(v2 * t * (1.f/6.f));
                }
                C[(size_t)r0 * N + col]       = v0;
                C[(size_t)(r0 + 8) * N + col] = v2;
            }
        }
    }
}

/* ------------------------------------------------------------------ */
/* Causal conv (K=4) + SiLU, smem-tiled                                */
/* ------------------------------------------------------------------ */
#define CCH 160
__global__ void __launch_bounds__(320)
conv_kernel(const float* __restrict__ w, const float* __restrict__ cb)
{
    __shared__ float sc[67 * CCH];
    int bc = blockIdx.x;
    int ct = blockIdx.y;
    int b = bc / NC, c = bc % NC;
    int l0 = c * 64;
    int ch0 = ct * CCH;
    int tid = threadIdx.x;

    for (int i = tid; i < 67 * (CCH/4); i += 320) {
        int r = i / (CCH/4), c4 = (i % (CCH/4)) * 4;
        int ls = l0 - 3 + r;
        float4 v = make_float4(0.f, 0.f, 0.f, 0.f);
        if (ls >= 0)
            v = *(const float4*)(g_zxbcdt +
                (size_t)(b * L_SZ + ls) * DPROJ + DINNER + ch0 + c4);
        *(float4*)&sc[r * CCH + c4] = v;
    }
    __syncthreads();

    int cg = tid % 40;
    int lb = tid / 40;
    int ch = ch0 + cg * 4;
    float wr[4][4];
#pragma unroll
    for (int j = 0; j < 4; j++)
#pragma unroll
        for (int k = 0; k < 4; k++)
            wr[j][k] = __ldg(&w[(ch + j) * 4 + k]);
    float4 cbv = *(const float4*)(cb + ch);

#pragma unroll
    for (int pass = 0; pass < 8; pass++) {
        int l = lb + pass * 8;
        float4 acc = cbv;
#pragma unroll
        for (int k = 0; k < 4; k++) {
            float4 xv = *(float4*)&sc[(l + k) * CCH + cg * 4];
            acc.x += xv.x * wr[0][k];
            acc.y += xv.y * wr[1][k];
            acc.z += xv.z * wr[2][k];
            acc.w += xv.w * wr[3][k];
        }
        acc.x = acc.x / (1.f + __expf(-acc.x));
        acc.y = acc.y / (1.f + __expf(-acc.y));
        acc.z = acc.z / (1.f + __expf(-acc.z));
        acc.w = acc.w / (1.f + __expf(-acc.w));
        *(float4*)(g_xbc + (size_t)(b * L_SZ + l0 + l) * CONVD + ch) = acc;
    }
}

/* fused softplus(dt) + per-chunk cumsum + chunk decay                 */
__global__ void acs_fused(const float* __restrict__ dtb,
                          const float* __restrict__ A_log)
{
    __shared__ float sh[64];
    int id = blockIdx.x;                 /* (b*NH+h)*NC + c */
    int c  = id % NC;
    int bh = id / NC;
    int h  = bh % NH;
    int b  = bh / NH;
    int l  = threadIdx.x;
    int r  = b * L_SZ + c * 64 + l;

    float v = g_zxbcdt[(size_t)r * DPROJ + (DPROJ - NH) + h] + __ldg(&dtb[h]);
    float dtv = (v > 20.f) ? v : log1pf(__expf(v));
    g_dtsp[(size_t)r * NH + h] = dtv;

    float Ah = -expf(__ldg(&A_log[h]));
    sh[l] = dtv * Ah;
    __syncthreads();
    for (int off = 1; off < 64; off <<= 1) {
        float t = (l >= off) ? sh[l - off] : 0.f;
        __syncthreads();
        sh[l] += t;
        __syncthreads();
    }
    g_acs[(size_t)id * 64 + l] = sh[l];
    if (l == 63) g_cdec[id] = __expf(sh[63]);
}

/* ------------------------------------------------------------------ */
#define SR 68
#define SZT (64*SR)

__device__ __forceinline__ void mm64(const float* __restrict__ sA,
                                     const float* __restrict__ sB,
                                     int wm, int wn, int g, int tg,
                                     float acc[4][4])
{
#pragma unroll
    for (int k0 = 0; k0 < 64; k0 += 8) {
        uint32_t a0 = f2tf32(sA[(wm + g)     * SR + k0 + tg]);
        uint32_t a1 = f2tf32(sA[(wm + 8 + g) * SR + k0 + tg]);
        uint32_t a2 = f2tf32(sA[(wm + g)     * SR + k0 + 4 + tg]);
        uint32_t a3 = f2tf32(sA[(wm + 8 + g) * SR + k0 + 4 + tg]);
#pragma unroll
        for (int nt = 0; nt < 4; nt++) {
            uint32_t b0 = f2tf32(sB[(wn + nt * 8 + g) * SR + k0 + tg]);
            uint32_t b1 = f2tf32(sB[(wn + nt * 8 + g) * SR + k0 + 4 + tg]);
            mma_tf32(acc[nt], a0, a1, a2, a3, b0, b1);
        }
    }
}

/* ------------------------------------------------------------------ */
/* Chunk kernel: G = C·B^T -> g_G ; states per head -> g_states        */
/* ------------------------------------------------------------------ */
extern __shared__ float smem[];
__global__ void __launch_bounds__(256, 3)
chunk_kernel(void)
{
    float* sB   = smem;
    float* sBt  = smem + SZT;
    float* sC   = smem + 2*SZT;
    float* sXdt = smem + 3*SZT;
    float* sDec = smem + 4*SZT;
    float* sDt  = smem + 4*SZT + 64;

    int bc = blockIdx.x;
    int b = bc / NC, c = bc % NC;
    int tid = threadIdx.x;
    int base = b * L_SZ + c * CHUNK;

    int warp = tid >> 5, lane = tid & 31;
    int g  = lane >> 2, tg = lane & 3;
    int wm = (warp >> 1) * 16;
    int wn = (warp & 1) * 32;

    for (int i = tid; i < 1024; i += 256) {
        int l = i >> 4, n4 = (i & 15) * 4;
        const float* row = g_xbc + (size_t)(base + l) * CONVD + DINNER;
        float4 bv = *(const float4*)(row + n4);
        float4 cv = *(const float4*)(row + DSTATE + n4);
        *(float4*)&sB[l * SR + n4] = bv;
        *(float4*)&sC[l * SR + n4] = cv;
        sBt[(n4 + 0) * SR + l] = bv.x;
        sBt[(n4 + 1) * SR + l] = bv.y;
        sBt[(n4 + 2) * SR + l] = bv.z;
        sBt[(n4 + 3) * SR + l] = bv.w;
    }
    __syncthreads();

    {
        float acc[4][4];
#pragma unroll
        for (int i = 0; i < 4; i++)
#pragma unroll
            for (int j = 0; j < 4; j++) acc[i][j] = 0.f;
        mm64(sC, sB, wm, wn, g, tg, acc);
        float* gp = g_G + (size_t)bc * 4096;
#pragma unroll
        for (int nt = 0; nt < 4; nt++) {
            int cl = wn + nt * 8 + 2 * tg;
            *(float2*)(gp + (wm + g)     * 64 + cl) = make_float2(acc[nt][0], acc[nt][1]);
            *(float2*)(gp + (wm + 8 + g) * 64 + cl) = make_float2(acc[nt][2], acc[nt][3]);
        }
    }

    for (int h = 0; h < NH; h++) {
        __syncthreads();
        if (tid < 64) {
            sDt[tid] = g_dtsp[(size_t)(base + tid) * NH + h];
            const float* ac = g_acs + ((size_t)(b * NH + h) * NC + c) * 64;
            sDec[tid] = __expf(ac[63] - ac[tid]);
        }
        __syncthreads();

        for (int i = tid; i < 1024; i += 256) {
            int s = i >> 4, p4 = (i & 15) * 4;
            float4 xv = *(const float4*)(g_xbc + (size_t)(base + s) * CONVD + h * HD + p4);
            float sc = sDt[s] * sDec[s];
            sXdt[(p4 + 0) * SR + s] = xv.x * sc;
            sXdt[(p4 + 1) * SR + s] = xv.y * sc;
            sXdt[(p4 + 2) * SR + s] = xv.z * sc;
            sXdt[(p4 + 3) * SR + s] = xv.w * sc;
        }
        __syncthreads();

        float acc[4][4];
#pragma unroll
        for (int i = 0; i < 4; i++)
#pragma unroll
            for (int j = 0; j < 4; j++) acc[i][j] = 0.f;
        mm64(sBt, sXdt, wm, wn, g, tg, acc);
        float* sp = g_states + (((size_t)bc * NH + h) << 12);
#pragma unroll
        for (int nt = 0; nt < 4; nt++) {
            int p = wn + nt * 8 + 2 * tg;
            *(float2*)(sp + (wm + g)     * 64 + p) = make_float2(acc[nt][0], acc[nt][1]);
            *(float2*)(sp + (wm + 8 + g) * 64 + p) = make_float2(acc[nt][2], acc[nt][3]);
        }
    }
}

/* sequential inter-chunk state recurrence                              */
__global__ void scan_kernel(void)
{
    int idx = blockIdx.x * blockDim.x + threadIdx.x;
    int e = idx & 4095;
    int h = (idx >> 12) & 7;
    int b = idx >> 15;
    float carry = 0.f;
    for (int c = 0; c < NC; c++) {
        size_t off = (((size_t)(b * NC + c) * NH + h) << 12) + e;
        g_prev[off] = carry;
        carry = carry * g_cdec[(b * NH + h) * NC + c] + g_states[off];
    }
}

/* ------------------------------------------------------------------ */
/* ssd_y: Y = M·X + E·(C·prev^T) + Dp·X, gated by silu(z).            */
/* dt folded into M; sXt holds RAW X.                                  */
/* ------------------------------------------------------------------ */
__global__ void __launch_bounds__(256, 3)
ssd_y(const float* __restrict__ Dp)
{
    float* sC   = smem;
    float* sG   = smem + SZT;
    float* sT   = smem + 2*SZT;
    float* sXt  = smem + 3*SZT;
    float* sE   = smem + 4*SZT;
    float* sAcs = smem + 4*SZT + 64;
    float* sDt  = smem + 4*SZT + 128;
    float* sSS  = smem + 4*SZT + 192;

    int bc = blockIdx.x;
    int b = bc / NC, c = bc % NC;
    int tid = threadIdx.x;
    int base = b * L_SZ + c * CHUNK;

    int warp = tid >> 5, lane = tid & 31;
    int g  = lane >> 2, tg = lane & 3;
    int wm = (warp >> 1) * 16;
    int wn = (warp & 1) * 32;
    int r0 = wm + g, r1 = wm + 8 + g;

    const float* gp = g_G + (size_t)bc * 4096;
    for (int i = tid; i < 1024; i += 256) {
        int l = i >> 4, n4 = (i & 15) * 4;
        *(float4*)&sC[l * SR + n4] =
            *(const float4*)(g_xbc + (size_t)(base + l) * CONVD + DINNER + DSTATE + n4);
        *(float4*)&sG[l * SR + n4] = *(const float4*)(gp + l * 64 + n4);
    }
    if (tid < 64) sSS[tid] = 0.f;
    __syncthreads();

    float ss0 = 0.f, ss1 = 0.f;

    for (int h = 0; h < NH; h++) {
        if (tid < 64) {
            const float* ac = g_acs + ((size_t)(b * NH + h) * NC + c) * 64;
            float a = ac[tid];
            sAcs[tid] = a;
            sE[tid]   = __expf(a);
            sDt[tid]  = g_dtsp[(size_t)(base + tid) * NH + h];
        }
        __syncthreads();

        /* M[l][s] (dt folded) into sT */
        for (int i = tid; i < 4096; i += 256) {
            int l = i >> 6, s = i & 63;
            sT[l * SR + s] = (s <= l)
                ? sG[l * SR + s] * __expf(sAcs[l] - sAcs[s]) * sDt[s] : 0.f;
        }
        /* Xt[p][s] = RAW X[s][p] */
        for (int i = tid; i < 1024; i += 256) {
            int s = i >> 4, p4 = (i & 15) * 4;
            float4 xv = *(const float4*)(g_xbc + (size_t)(base + s) * CONVD + h * HD + p4);
            sXt[(p4 + 0) * SR + s] = xv.x;
            sXt[(p4 + 1) * SR + s] = xv.y;
            sXt[(p4 + 2) * SR + s] = xv.z;
            sXt[(p4 + 3) * SR + s] = xv.w;
        }
        __syncthreads();

        /* Y_diag = M·X */
        float accY[4][4];
#pragma unroll
        for (int i = 0; i < 4; i++)
#pragma unroll
            for (int j = 0; j < 4; j++) accY[i][j] = 0.f;
        mm64(sT, sXt, wm, wn, g, tg, accY);
        __syncthreads();

        /* prev^T into sT */
        const float* pv = g_prev + (((size_t)bc * NH + h) << 12);
        for (int i = tid; i < 1024; i += 256) {
            int n = i >> 4, p4 = (i & 15) * 4;
            float4 pvv = *(const float4*)(pv + n * 64 + p4);
            sT[(p4 + 0) * SR + n] = pvv.x;
            sT[(p4 + 1) * SR + n] = pvv.y;
            sT[(p4 + 2) * SR + n] = pvv.z;
            sT[(p4 + 3) * SR + n] = pvv.w;
        }
        __syncthreads();

        float accO[4][4];
#pragma unroll
        for (int i = 0; i < 4; i++)
#pragma unroll
            for (int j = 0; j < 4; j++) accO[i][j] = 0.f;
        mm64(sC, sT, wm, wn, g, tg, accO);

        float Dph = __ldg(&Dp[h]);
        float e0 = sE[r0], e1 = sE[r1];
#pragma unroll
        for (int nt = 0; nt < 4; nt++) {
            int p = wn + nt * 8 + 2 * tg;
            float x00 = sXt[(p + 0) * SR + r0];
            float x01 = sXt[(p + 1) * SR + r0];
            float x10 = sXt[(p + 0) * SR + r1];
            float x11 = sXt[(p + 1) * SR + r1];
            float2 z0 = *(const float2*)(g_zxbcdt + (size_t)(base + r0) * DPROJ + h * HD + p);
            float2 z1 = *(const float2*)(g_zxbcdt + (size_t)(base + r1) * DPROJ + h * HD + p);
            float y00 = accY[nt][0] + e0 * accO[nt][0] + Dph * x00;
            float y01 = accY[nt][1] + e0 * accO[nt][1] + Dph * x01;
            float y10 = accY[nt][2] + e1 * accO[nt][2] + Dph * x10;
            float y11 = accY[nt][3] + e1 * accO[nt][3] + Dph * x11;
            float u00 = y00 * (z0.x / (1.f + __expf(-z0.x)));
            float u01 = y01 * (z0.y / (1.f + __expf(-z0.y)));
            float u10 = y10 * (z1.x / (1.f + __expf(-z1.x)));
            float u11 = y11 * (z1.y / (1.f + __expf(-z1.y)));
            ss0 += u00 * u00 + u01 * u01;
            ss1 += u10 * u10 + u11 * u11;
            *(float2*)(g_yn + (size_t)(base + r0) * DINNER + h * HD + p) =
                make_float2(tf32r(u00), tf32r(u01));
            *(float2*)(g_yn + (size_t)(base + r1) * DINNER + h * HD + p) =
                make_float2(tf32r(u10), tf32r(u11));
        }
        __syncthreads();
    }

    atomicAdd(&sSS[r0], ss0);
    atomicAdd(&sSS[r1], ss1);
    __syncthreads();
    if (tid < 64)
        g_scale[base + tid] = rsqrtf(sSS[tid] / 512.f + 1e-12f);
}

/* LayerNorm(a + res) * g + b  -- warp per row                         */
__global__ void __launch_bounds__(256)
ln_res(const float* __restrict__ a, const float* __restrict__ res,
       const float* __restrict__ g, const float* __restrict__ bb,
       float* __restrict__ out, int rnd)
{
    int row  = blockIdx.x * 8 + (threadIdx.x >> 5);
    int lane = threadIdx.x & 31;
    const float* ar = a   + (size_t)row * 256;
    const float* rr = res + (size_t)row * 256;

    float v[8];
    float s = 0.f;
#pragma unroll
    for (int j = 0; j < 8; j++) {
        int cidx = lane + j * 32;
        v[j] = ar[cidx] + rr[cidx];
        s += v[j];
    }
#pragma unroll
    for (int o = 16; o > 0; o >>= 1) s += __shfl_xor_sync(0xffffffff, s, o);
    float mean = s * (1.f / 256.f);

    float vs = 0.f;
#pragma unroll
    for (int j = 0; j < 8; j++) {
        float d = v[j] - mean;
        vs += d * d;
    }
#pragma unroll
    for (int o = 16; o > 0; o >>= 1) vs += __shfl_xor_sync(0xffffffff, vs, o);
    float inv = rsqrtf(vs * (1.f / 256.f) + 1e-12f);

    float* orow = out + (size_t)row * 256;
#pragma unroll
    for (int j = 0; j < 8; j++) {
        int cidx = lane + j * 32;
        float o = (v[j] - mean) * inv * g[cidx] + bb[cidx];
        orow[cidx] = rnd ? tf32r(o) : o;
    }
}

/* ------------------------------------------------------------------ */
extern "C" void kernel_launch(void* const* d_in, const int* in_sizes, int n_in,
                              void* d_out, int out_size)
{
    const float* x       = (const float*)d_in[0];
    const float* in_w    = (const float*)d_in[1];
    const float* in_b    = (const float*)d_in[2];
    const float* conv_w  = (const float*)d_in[3];
    const float* conv_b  = (const float*)d_in[4];
    const float* dt_bias = (const float*)d_in[5];
    const float* A_log   = (const float*)d_in[6];
    const float* Dp      = (const float*)d_in[7];
    const float* norm_w  = (const float*)d_in[8];
    const float* out_w   = (const float*)d_in[9];
    const float* out_b   = (const float*)d_in[10];
    const float* ln_g    = (const float*)d_in[11];
    const float* ln_b    = (const float*)d_in[12];
    const float* fc1_w   = (const float*)d_in[13];
    const float* fc1_b   = (const float*)d_in[14];
    const float* fc2_w   = (const float*)d_in[15];
    const float* fc2_b   = (const float*)d_in[16];
    const float* fln_g   = (const float*)d_in[17];
    const float* fln_b   = (const float*)d_in[18];
    float* out = (float*)d_out;

    void *p;
    cudaGetSymbolAddress(&p, g_zxbcdt);  float* zx     = (float*)p;
    cudaGetSymbolAddress(&p, g_yn);      float* yn     = (float*)p;
    cudaGetSymbolAddress(&p, g_t256);    float* t256   = (float*)p;
    cudaGetSymbolAddress(&p, g_hidden);  float* hidden = (float*)p;
    cudaGetSymbolAddress(&p, g_h1);      float* h1     = (float*)p;
    cudaGetSymbolAddress(&p, g_wtf);     float* wtf    = (float*)p;
    cudaGetSymbolAddress(&p, g_scale);   float* rscale = (float*)p;

    static int chunk_smem = (4 * SZT + 128) * 4;
    static int ssdy_smem  = (4 * SZT + 256) * 4;
    cudaFuncSetAttribute(chunk_kernel,
                         cudaFuncAttributeMaxDynamicSharedMemorySize, chunk_smem);
    cudaFuncSetAttribute(ssd_y,
                         cudaFuncAttributeMaxDynamicSharedMemorySize, ssdy_smem);
    cudaFuncSetAttribute(gemm_tf32,
                         cudaFuncAttributeMaxDynamicSharedMemorySize, 110592);

    /* 0. weight tf32 conversions (norm_w folded into out_w) */
    cvt_tf32<<<(DPROJ*DMODEL + 255)/256, 256>>>(in_w,  wtf + W_IN_OFF,  DPROJ*DMODEL);
    cvt_tf32_nw<<<(DMODEL*DINNER + 255)/256, 256>>>(out_w, norm_w,
                                                    wtf + W_OUT_OFF, DMODEL*DINNER);
    cvt_tf32<<<(DFFN*DMODEL + 255)/256, 256>>>(fc1_w,  wtf + W_FC1_OFF, DFFN*DMODEL);
    cvt_tf32<<<(DMODEL*DFFN + 255)/256, 256>>>(fc2_w,  wtf + W_FC2_OFF, DMODEL*DFFN);

    /* 1. in_proj (A fragments converted inline) */
    gemm_tf32<<<dim3((DPROJ + 127) / 128, NROWS / 128), 128, 110592>>>(
        x, wtf + W_IN_OFF, in_b, zx, NULL, NROWS, DPROJ, DMODEL, 0, 1);
    /* 2-3 */
    conv_kernel<<<dim3(B_SZ * NC, CONVD / CCH), 320>>>(conv_w, conv_b);
    acs_fused<<<B_SZ * NH * NC, 64>>>(dt_bias, A_log);
    /* 5. intra-chunk */
    chunk_kernel<<<B_SZ * NC, 256, chunk_smem>>>();
    /* 6. inter-chunk scan */
    scan_kernel<<<(B_SZ * NH * HD * DSTATE + 255) / 256, 256>>>();
    /* 7. Y + gate */
    ssd_y<<<B_SZ * NC, 256, ssdy_smem>>>(Dp);
    /* 9. out_proj with deferred RMS row-scale */
    gemm_tf32<<<dim3(DMODEL / 128, NROWS / 128), 128, 110592>>>(
        yn, wtf + W_OUT_OFF, out_b, t256, rscale, NROWS, DMODEL, DINNER, 0, 0);
    /* 10 */
    ln_res<<<NROWS / 8, 256>>>(t256, x, ln_g, ln_b, hidden, 1);
    /* 11 */
    gemm_tf32<<<dim3(DFFN / 128, NROWS / 128), 128, 110592>>>(
        hidden, wtf + W_FC1_OFF, fc1_b, h1, NULL, NROWS, DFFN, DMODEL, 1, 0);
    /* 12 */
    gemm_tf32<<<dim3(DMODEL / 128, NROWS / 128), 128, 110592>>>(
        h1, wtf + W_FC2_OFF, fc2_b, t256, NULL, NROWS, DMODEL, DFFN, 0, 0);
    /* 13 */
    ln_res<<<NROWS / 8, 256>>>(t256, hidden, fln_g, fln_b, out, 0);
}

// round 16
// speedup vs baseline: 1.2646x; 1.0317x over previous
#include <cuda_runtime.h>
#include <math.h>
#include <stdint.h>

#define B_SZ    32
#define L_SZ    2048
#define NROWS   (B_SZ*L_SZ)      /* 65536 */
#define DMODEL  256
#define DINNER  512
#define NH      8
#define HD      64
#define DSTATE  64
#define CHUNK   64
#define NC      (L_SZ/CHUNK)     /* 32 */
#define CONVD   640
#define DPROJ   1160
#define DFFN    1024

/* ------------------------------------------------------------------ */
__device__ float g_zxbcdt[(size_t)NROWS*DPROJ];
__device__ float g_xbc[(size_t)NROWS*CONVD];
__device__ float g_dtsp[(size_t)NROWS*NH];
__device__ float g_acs[(size_t)B_SZ*NH*L_SZ];
__device__ float g_cdec[B_SZ*NH*NC];
__device__ float g_G[(size_t)B_SZ*NC*CHUNK*CHUNK];
__device__ float g_states[(size_t)B_SZ*NC*NH*HD*DSTATE];  /* [n][p] */
__device__ float g_prev[(size_t)B_SZ*NC*NH*HD*DSTATE];    /* [n][p] */
__device__ float g_yn[(size_t)NROWS*DINNER];              /* unnormalized u */
__device__ float g_scale[(size_t)NROWS];
__device__ float g_ss2[(size_t)NROWS];                    /* partial sum u^2 */
__device__ float g_t256[(size_t)NROWS*DMODEL];
__device__ float g_hidden[(size_t)NROWS*DMODEL];
__device__ float g_h1[(size_t)NROWS*DFFN];

#define W_IN_OFF   0
#define W_OUT_OFF  (DPROJ*DMODEL)
#define W_FC1_OFF  (W_OUT_OFF + DMODEL*DINNER)
#define W_FC2_OFF  (W_FC1_OFF + DFFN*DMODEL)
#define W_TOTAL    (W_FC2_OFF + DMODEL*DFFN)
__device__ float g_wtf[W_TOTAL];

__device__ __forceinline__ uint32_t f2tf32(float v) {
    uint32_t r;
    asm("cvt.rna.tf32.f32 %0, %1;" : "=r"(r) : "f"(v));
    return r;
}
__device__ __forceinline__ float tf32r(float v) {
    return __uint_as_float(f2tf32(v));
}

/* single fused weight convert: in_w | out_w*norm_w | fc1_w | fc2_w    */
__global__ void cvt_weights(const float* __restrict__ in_w,
                            const float* __restrict__ out_w,
                            const float* __restrict__ fc1_w,
                            const float* __restrict__ fc2_w,
                            const float* __restrict__ nw)
{
    int i = blockIdx.x * blockDim.x + threadIdx.x;
    if (i >= W_TOTAL) return;
    float v;
    if (i < W_OUT_OFF)        v = in_w[i];
    else if (i < W_FC1_OFF) { int j = i - W_OUT_OFF; v = out_w[j] * nw[j & (DINNER-1)]; }
    else if (i < W_FC2_OFF)   v = fc1_w[i - W_FC1_OFF];
    else                      v = fc2_w[i - W_FC2_OFF];
    g_wtf[i] = tf32r(v);
}

/* ------------------------------------------------------------------ */
__device__ __forceinline__ void mma_tf32(float c[4],
    uint32_t a0, uint32_t a1, uint32_t a2, uint32_t a3,
    uint32_t b0, uint32_t b1)
{
    asm volatile(
        "mma.sync.aligned.m16n8k8.row.col.f32.tf32.tf32.f32 "
        "{%0,%1,%2,%3}, {%4,%5,%6,%7}, {%8,%9}, {%0,%1,%2,%3};"
        : "+f"(c[0]), "+f"(c[1]), "+f"(c[2]), "+f"(c[3])
        : "r"(a0), "r"(a1), "r"(a2), "r"(a3), "r"(b0), "r"(b1));
}

/* ------------------------------------------------------------------ */
/* tf32 tensor-core GEMM, 3-stage cp.async pipeline                    */
/* ------------------------------------------------------------------ */
#define SROW 36
#define TBUF (128*SROW)

__device__ __forceinline__ void cpa16(uint32_t sdst, const float* gsrc) {
    asm volatile("cp.async.cg.shared.global [%0], [%1], 16;"
                 :: "r"(sdst), "l"(gsrc));
}
__device__ __forceinline__ void cpa16z(uint32_t sdst, const float* gsrc, int valid) {
    int sz = valid ? 16 : 0;
    asm volatile("cp.async.cg.shared.global [%0], [%1], 16, %2;"
                 :: "r"(sdst), "l"(gsrc), "r"(sz));
}

__global__ void __launch_bounds__(128, 2)
gemm_tf32(const float* __restrict__ A, const float* __restrict__ W,
          const float* __restrict__ bias, float* __restrict__ C,
          const float* __restrict__ rowscale,
          int M, int N, int K, int act, int cvtA)
{
    extern __shared__ float sm[];
    float* As = sm;
    float* Ws = sm + 3 * TBUF;
    uint32_t sAs = (uint32_t)__cvta_generic_to_shared(As);
    uint32_t sWs = (uint32_t)__cvta_generic_to_shared(Ws);

    int tid  = threadIdx.x;
    int warp = tid >> 5, lane = tid & 31;
    int wm = (warp >> 1) * 64;
    int wn = (warp & 1) * 64;
    int m0 = blockIdx.y * 128;
    int n0 = blockIdx.x * 128;
    int g  = lane >> 2;
    int tg = lane & 3;

    float acc[4][8][4];
#pragma unroll
    for (int i = 0; i < 4; i++)
#pragma unroll
        for (int j = 0; j < 8; j++)
#pragma unroll
            for (int r = 0; r < 4; r++) acc[i][j][r] = 0.f;

    int ntiles = K >> 5;

#define FILL(BUF, K0) do {                                                   \
    int _k0 = (K0);                                                          \
    _Pragma("unroll")                                                        \
    for (int i = 0; i < 8; i++) {                                            \
        int c = tid + i * 128;                                               \
        int row = c >> 3, cc = (c & 7) * 4;                                  \
        cpa16(sAs + (((BUF)*TBUF + row*SROW + cc) << 2),                     \
              A + (size_t)(m0 + row) * K + _k0 + cc);                        \
        int wr = n0 + row;                                                   \
        int wv = wr < N;                                                     \
        cpa16z(sWs + (((BUF)*TBUF + row*SROW + cc) << 2),                    \
               W + (size_t)(wv ? wr : 0) * K + _k0 + cc, wv);                \
    }                                                                        \
    asm volatile("cp.async.commit_group;");                                  \
} while (0)

    FILL(0, 0);
    if (ntiles > 1) FILL(1, 32);
    for (int kt = 0; kt < ntiles; kt++) {
        if (kt + 2 < ntiles) {
            FILL((kt + 2) % 3, (kt + 2) * 32);
            asm volatile("cp.async.wait_group 2;");
        } else if (kt + 1 < ntiles) {
            asm volatile("cp.async.wait_group 1;");
        } else {
            asm volatile("cp.async.wait_group 0;");
        }
        __syncthreads();

        int buf = kt % 3;
        const uint32_t* Ab = (const uint32_t*)(As + buf * TBUF);
        const uint32_t* Wb = (const uint32_t*)(Ws + buf * TBUF);
#pragma unroll
        for (int ks = 0; ks < 4; ks++) {
            int k0 = ks * 8;
            uint32_t af[4][4];
#pragma unroll
            for (int mt = 0; mt < 4; mt++) {
                const uint32_t* ap = Ab + (wm + mt * 16 + g) * SROW + k0 + tg;
                af[mt][0] = ap[0];
                af[mt][1] = ap[8 * SROW];
                af[mt][2] = ap[4];
                af[mt][3] = ap[8 * SROW + 4];
            }
            if (cvtA) {
#pragma unroll
                for (int mt = 0; mt < 4; mt++)
#pragma unroll
                    for (int i = 0; i < 4; i++)
                        af[mt][i] = f2tf32(__uint_as_float(af[mt][i]));
            }
            uint32_t bf[8][2];
#pragma unroll
            for (int nt = 0; nt < 8; nt++) {
                const uint32_t* bp = Wb + (wn + nt * 8 + g) * SROW + k0 + tg;
                bf[nt][0] = bp[0];
                bf[nt][1] = bp[4];
            }
#pragma unroll
            for (int mt = 0; mt < 4; mt++)
#pragma unroll
                for (int nt = 0; nt < 8; nt++)
                    mma_tf32(acc[mt][nt], af[mt][0], af[mt][1], af[mt][2],
                             af[mt][3], bf[nt][0], bf[nt][1]);
        }
        __syncthreads();
    }

#pragma unroll
    for (int mt = 0; mt < 4; mt++) {
        int r0 = m0 + wm + mt * 16 + g;
        float s0 = rowscale ? rowscale[r0]     : 1.f;
        float s2 = rowscale ? rowscale[r0 + 8] : 1.f;
#pragma unroll
        for (int nt = 0; nt < 8; nt++) {
            int col = n0 + wn + nt * 8 + 2 * tg;
            if (col + 1 < N) {
                float b0 = bias[col], b1 = bias[col + 1];
                float v0 = acc[mt][nt][0] * s0 + b0;
                float v1 = acc[mt][nt][1] * s0 + b1;
                float v2 = acc[mt][nt][2] * s2 + b0;
                float v3 = acc[mt][nt][3] * s2 + b1;
                if (act == 1) {
                    float t;
                    t = fminf(fmaxf(v0 + 3.f, 0.f), 6.f); v0 = tf32r(v0 * t * (1.f/6.f));
                    t = fminf(fmaxf(v1 + 3.f, 0.f), 6.f); v1 = tf32r(v1 * t * (1.f/6.f));
                    t = fminf(fmaxf(v2 + 3.f, 0.f), 6.f); v2 = tf32r(v2 * t * (1.f/6.f));
                    t = fminf(fmaxf(v3 + 3.f, 0.f), 6.f); v3 = tf32r(v3 * t * (1.f/6.f));
                }
                *(float2*)(C + (size_t)r0 * N + col)       = make_float2(v0, v1);
                *(float2*)(C + (size_t)(r0 + 8) * N + col) = make_float2(v2, v3);
            } else if (col < N) {
                float b0 = bias[col];
                float v0 = acc[mt][nt][0] * s0 + b0;
                float v2 = acc[mt][nt][2] * s2 + b0;
                if (act == 1) {
                    float t;
                    t = fminf(fmaxf(v0 + 3.f, 0.f), 6.f); v0 = tf32r(v0 * t * (1.f/6.f));
                    t = fminf(fmaxf(v2 + 3.f, 0.f), 6.f); v2 = tf32r(v2 * t * (1.f/6.f));
                }
                C[(size_t)r0 * N + col]       = v0;
                C[(size_t)(r0 + 8) * N + col] = v2;
            }
        }
    }
}

/* ------------------------------------------------------------------ */
/* Causal conv (K=4) + SiLU, smem-tiled                                */
/* ------------------------------------------------------------------ */
#define CCH 160
__global__ void __launch_bounds__(320)
conv_kernel(const float* __restrict__ w, const float* __restrict__ cb)
{
    __shared__ float sc[67 * CCH];
    int bc = blockIdx.x;
    int ct = blockIdx.y;
    int b = bc / NC, c = bc % NC;
    int l0 = c * 64;
    int ch0 = ct * CCH;
    int tid = threadIdx.x;

    for (int i = tid; i < 67 * (CCH/4); i += 320) {
        int r = i / (CCH/4), c4 = (i % (CCH/4)) * 4;
        int ls = l0 - 3 + r;
        float4 v = make_float4(0.f, 0.f, 0.f, 0.f);
        if (ls >= 0)
            v = *(const float4*)(g_zxbcdt +
                (size_t)(b * L_SZ + ls) * DPROJ + DINNER + ch0 + c4);
        *(float4*)&sc[r * CCH + c4] = v;
    }
    __syncthreads();

    int cg = tid % 40;
    int lb = tid / 40;
    int ch = ch0 + cg * 4;
    float wr[4][4];
#pragma unroll
    for (int j = 0; j < 4; j++)
#pragma unroll
        for (int k = 0; k < 4; k++)
            wr[j][k] = __ldg(&w[(ch + j) * 4 + k]);
    float4 cbv = *(const float4*)(cb + ch);

#pragma unroll
    for (int pass = 0; pass < 8; pass++) {
        int l = lb + pass * 8;
        float4 acc = cbv;
#pragma unroll
        for (int k = 0; k < 4; k++) {
            float4 xv = *(float4*)&sc[(l + k) * CCH + cg * 4];
            acc.x += xv.x * wr[0][k];
            acc.y += xv.y * wr[1][k];
            acc.z += xv.z * wr[2][k];
            acc.w += xv.w * wr[3][k];
        }
        acc.x = acc.x / (1.f + __expf(-acc.x));
        acc.y = acc.y / (1.f + __expf(-acc.y));
        acc.z = acc.z / (1.f + __expf(-acc.z));
        acc.w = acc.w / (1.f + __expf(-acc.w));
        *(float4*)(g_xbc + (size_t)(b * L_SZ + l0 + l) * CONVD + ch) = acc;
    }
}

/* fused softplus(dt) + per-chunk cumsum + chunk decay                 */
__global__ void acs_fused(const float* __restrict__ dtb,
                          const float* __restrict__ A_log)
{
    __shared__ float sh[64];
    int id = blockIdx.x;
    int c  = id % NC;
    int bh = id / NC;
    int h  = bh % NH;
    int b  = bh / NH;
    int l  = threadIdx.x;
    int r  = b * L_SZ + c * 64 + l;

    float v = g_zxbcdt[(size_t)r * DPROJ + (DPROJ - NH) + h] + __ldg(&dtb[h]);
    float dtv = (v > 20.f) ? v : log1pf(__expf(v));
    g_dtsp[(size_t)r * NH + h] = dtv;

    float Ah = -expf(__ldg(&A_log[h]));
    sh[l] = dtv * Ah;
    __syncthreads();
    for (int off = 1; off < 64; off <<= 1) {
        float t = (l >= off) ? sh[l - off] : 0.f;
        __syncthreads();
        sh[l] += t;
        __syncthreads();
    }
    g_acs[(size_t)id * 64 + l] = sh[l];
    if (l == 63) g_cdec[id] = __expf(sh[63]);
}

/* ------------------------------------------------------------------ */
#define SR 68
#define SZT (64*SR)

__device__ __forceinline__ void mm64(const float* __restrict__ sA,
                                     const float* __restrict__ sB,
                                     int wm, int wn, int g, int tg,
                                     float acc[4][4])
{
#pragma unroll
    for (int k0 = 0; k0 < 64; k0 += 8) {
        uint32_t a0 = f2tf32(sA[(wm + g)     * SR + k0 + tg]);
        uint32_t a1 = f2tf32(sA[(wm + 8 + g) * SR + k0 + tg]);
        uint32_t a2 = f2tf32(sA[(wm + g)     * SR + k0 + 4 + tg]);
        uint32_t a3 = f2tf32(sA[(wm + 8 + g) * SR + k0 + 4 + tg]);
#pragma unroll
        for (int nt = 0; nt < 4; nt++) {
            uint32_t b0 = f2tf32(sB[(wn + nt * 8 + g) * SR + k0 + tg]);
            uint32_t b1 = f2tf32(sB[(wn + nt * 8 + g) * SR + k0 + 4 + tg]);
            mma_tf32(acc[nt], a0, a1, a2, a3, b0, b1);
        }
    }
}

/* ------------------------------------------------------------------ */
/* Chunk kernel: grid (B*NC, 2); y=0 also writes G; 4 heads per block  */
/* ------------------------------------------------------------------ */
extern __shared__ float smem[];
__global__ void __launch_bounds__(256, 3)
chunk_kernel(void)
{
    float* sB   = smem;
    float* sBt  = smem + SZT;
    float* sC   = smem + 2*SZT;
    float* sXdt = smem + 3*SZT;
    float* sDec = smem + 4*SZT;
    float* sDt  = smem + 4*SZT + 64;

    int bc = blockIdx.x;
    int hb = blockIdx.y;          /* head-half: 0 -> heads 0..3, 1 -> 4..7 */
    int b = bc / NC, c = bc % NC;
    int tid = threadIdx.x;
    int base = b * L_SZ + c * CHUNK;

    int warp = tid >> 5, lane = tid & 31;
    int g  = lane >> 2, tg = lane & 3;
    int wm = (warp >> 1) * 16;
    int wn = (warp & 1) * 32;

    for (int i = tid; i < 1024; i += 256) {
        int l = i >> 4, n4 = (i & 15) * 4;
        const float* row = g_xbc + (size_t)(base + l) * CONVD + DINNER;
        float4 bv = *(const float4*)(row + n4);
        *(float4*)&sB[l * SR + n4] = bv;
        sBt[(n4 + 0) * SR + l] = bv.x;
        sBt[(n4 + 1) * SR + l] = bv.y;
        sBt[(n4 + 2) * SR + l] = bv.z;
        sBt[(n4 + 3) * SR + l] = bv.w;
        if (hb == 0)
            *(float4*)&sC[l * SR + n4] = *(const float4*)(row + DSTATE + n4);
    }
    __syncthreads();

    if (hb == 0) {
        float acc[4][4];
#pragma unroll
        for (int i = 0; i < 4; i++)
#pragma unroll
            for (int j = 0; j < 4; j++) acc[i][j] = 0.f;
        mm64(sC, sB, wm, wn, g, tg, acc);
        float* gp = g_G + (size_t)bc * 4096;
#pragma unroll
        for (int nt = 0; nt < 4; nt++) {
            int cl = wn + nt * 8 + 2 * tg;
            *(float2*)(gp + (wm + g)     * 64 + cl) = make_float2(acc[nt][0], acc[nt][1]);
            *(float2*)(gp + (wm + 8 + g) * 64 + cl) = make_float2(acc[nt][2], acc[nt][3]);
        }
    }

    for (int hh = 0; hh < 4; hh++) {
        int h = hb * 4 + hh;
        __syncthreads();
        if (tid < 64) {
            sDt[tid] = g_dtsp[(size_t)(base + tid) * NH + h];
            const float* ac = g_acs + ((size_t)(b * NH + h) * NC + c) * 64;
            sDec[tid] = __expf(ac[63] - ac[tid]);
        }
        __syncthreads();

        for (int i = tid; i < 1024; i += 256) {
            int s = i >> 4, p4 = (i & 15) * 4;
            float4 xv = *(const float4*)(g_xbc + (size_t)(base + s) * CONVD + h * HD + p4);
            float sc = sDt[s] * sDec[s];
            sXdt[(p4 + 0) * SR + s] = xv.x * sc;
            sXdt[(p4 + 1) * SR + s] = xv.y * sc;
            sXdt[(p4 + 2) * SR + s] = xv.z * sc;
            sXdt[(p4 + 3) * SR + s] = xv.w * sc;
        }
        __syncthreads();

        float acc[4][4];
#pragma unroll
        for (int i = 0; i < 4; i++)
#pragma unroll
            for (int j = 0; j < 4; j++) acc[i][j] = 0.f;
        mm64(sBt, sXdt, wm, wn, g, tg, acc);
        float* sp = g_states + (((size_t)bc * NH + h) << 12);
#pragma unroll
        for (int nt = 0; nt < 4; nt++) {
            int p = wn + nt * 8 + 2 * tg;
            *(float2*)(sp + (wm + g)     * 64 + p) = make_float2(acc[nt][0], acc[nt][1]);
            *(float2*)(sp + (wm + 8 + g) * 64 + p) = make_float2(acc[nt][2], acc[nt][3]);
        }
    }
}

/* sequential inter-chunk state recurrence                              */
__global__ void scan_kernel(void)
{
    int idx = blockIdx.x * blockDim.x + threadIdx.x;
    int e = idx & 4095;
    int h = (idx >> 12) & 7;
    int b = idx >> 15;
    float carry = 0.f;
    for (int c = 0; c < NC; c++) {
        size_t off = (((size_t)(b * NC + c) * NH + h) << 12) + e;
        g_prev[off] = carry;
        carry = carry * g_cdec[(b * NH + h) * NC + c] + g_states[off];
    }
}

/* ------------------------------------------------------------------ */
/* ssd_y: grid (B*NC, 2), 4 heads per block. Partial sum(u^2) combined */
/* via g_ss2 (y=0 writes, y=1 adds in finish pass? -> use atomicAdd on */
/* global then separate tiny pass). Simpler: each block atomically adds*/
/* its partial to g_ss2; scale kernel computes rsqrt afterwards.       */
/* ------------------------------------------------------------------ */
__global__ void __launch_bounds__(256, 3)
ssd_y(const float* __restrict__ Dp)
{
    float* sC   = smem;
    float* sG   = smem + SZT;
    float* sT   = smem + 2*SZT;
    float* sXt  = smem + 3*SZT;
    float* sE   = smem + 4*SZT;
    float* sAcs = smem + 4*SZT + 64;
    float* sDt  = smem + 4*SZT + 128;
    float* sSS  = smem + 4*SZT + 192;

    int bc = blockIdx.x;
    int hb = blockIdx.y;
    int b = bc / NC, c = bc % NC;
    int tid = threadIdx.x;
    int base = b * L_SZ + c * CHUNK;

    int warp = tid >> 5, lane = tid & 31;
    int g  = lane >> 2, tg = lane & 3;
    int wm = (warp >> 1) * 16;
    int wn = (warp & 1) * 32;
    int r0 = wm + g, r1 = wm + 8 + g;

    const float* gp = g_G + (size_t)bc * 4096;
    for (int i = tid; i < 1024; i += 256) {
        int l = i >> 4, n4 = (i & 15) * 4;
        *(float4*)&sC[l * SR + n4] =
            *(const float4*)(g_xbc + (size_t)(base + l) * CONVD + DINNER + DSTATE + n4);
        *(float4*)&sG[l * SR + n4] = *(const float4*)(gp + l * 64 + n4);
    }
    if (tid < 64) sSS[tid] = 0.f;
    __syncthreads();

    float ss0 = 0.f, ss1 = 0.f;

    for (int hh = 0; hh < 4; hh++) {
        int h = hb * 4 + hh;
        if (tid < 64) {
            const float* ac = g_acs + ((size_t)(b * NH + h) * NC + c) * 64;
            float a = ac[tid];
            sAcs[tid] = a;
            sE[tid]   = __expf(a);
            sDt[tid]  = g_dtsp[(size_t)(base + tid) * NH + h];
        }
        __syncthreads();

        /* M[l][s] (dt folded) into sT */
        for (int i = tid; i < 4096; i += 256) {
            int l = i >> 6, s = i & 63;
            sT[l * SR + s] = (s <= l)
                ? sG[l * SR + s] * __expf(sAcs[l] - sAcs[s]) * sDt[s] : 0.f;
        }
        /* Xt[p][s] = RAW X[s][p] */
        for (int i = tid; i < 1024; i += 256) {
            int s = i >> 4, p4 = (i & 15) * 4;
            float4 xv = *(const float4*)(g_xbc + (size_t)(base + s) * CONVD + h * HD + p4);
            sXt[(p4 + 0) * SR + s] = xv.x;
            sXt[(p4 + 1) * SR + s] = xv.y;
            sXt[(p4 + 2) * SR + s] = xv.z;
            sXt[(p4 + 3) * SR + s] = xv.w;
        }
        __syncthreads();

        float accY[4][4];
#pragma unroll
        for (int i = 0; i < 4; i++)
#pragma unroll
            for (int j = 0; j < 4; j++) accY[i][j] = 0.f;
        mm64(sT, sXt, wm, wn, g, tg, accY);
        __syncthreads();

        const float* pv = g_prev + (((size_t)bc * NH + h) << 12);
        for (int i = tid; i < 1024; i += 256) {
            int n = i >> 4, p4 = (i & 15) * 4;
            float4 pvv = *(const float4*)(pv + n * 64 + p4);
            sT[(p4 + 0) * SR + n] = pvv.x;
            sT[(p4 + 1) * SR + n] = pvv.y;
            sT[(p4 + 2) * SR + n] = pvv.z;
            sT[(p4 + 3) * SR + n] = pvv.w;
        }
        __syncthreads();

        float accO[4][4];
#pragma unroll
        for (int i = 0; i < 4; i++)
#pragma unroll
            for (int j = 0; j < 4; j++) accO[i][j] = 0.f;
        mm64(sC, sT, wm, wn, g, tg, accO);

        float Dph = __ldg(&Dp[h]);
        float e0 = sE[r0], e1 = sE[r1];
#pragma unroll
        for (int nt = 0; nt < 4; nt++) {
            int p = wn + nt * 8 + 2 * tg;
            float x00 = sXt[(p + 0) * SR + r0];
            float x01 = sXt[(p + 1) * SR + r0];
            float x10 = sXt[(p + 0) * SR + r1];
            float x11 = sXt[(p + 1) * SR + r1];
            float2 z0 = *(const float2*)(g_zxbcdt + (size_t)(base + r0) * DPROJ + h * HD + p);
            float2 z1 = *(const float2*)(g_zxbcdt + (size_t)(base + r1) * DPROJ + h * HD + p);
            float y00 = accY[nt][0] + e0 * accO[nt][0] + Dph * x00;
            float y01 = accY[nt][1] + e0 * accO[nt][1] + Dph * x01;
            float y10 = accY[nt][2] + e1 * accO[nt][2] + Dph * x10;
            float y11 = accY[nt][3] + e1 * accO[nt][3] + Dph * x11;
            float u00 = y00 * (z0.x / (1.f + __expf(-z0.x)));
            float u01 = y01 * (z0.y / (1.f + __expf(-z0.y)));
            float u10 = y10 * (z1.x / (1.f + __expf(-z1.x)));
            float u11 = y11 * (z1.y / (1.f + __expf(-z1.y)));
            ss0 += u00 * u00 + u01 * u01;
            ss1 += u10 * u10 + u11 * u11;
            *(float2*)(g_yn + (size_t)(base + r0) * DINNER + h * HD + p) =
                make_float2(tf32r(u00), tf32r(u01));
            *(float2*)(g_yn + (size_t)(base + r1) * DINNER + h * HD + p) =
                make_float2(tf32r(u10), tf32r(u11));
        }
        __syncthreads();
    }

    atomicAdd(&sSS[r0], ss0);
    atomicAdd(&sSS[r1], ss1);
    __syncthreads();
    if (tid < 64)
        atomicAdd(&g_ss2[base + tid], sSS[tid]);
}

/* zero partials; then rms finish computes scale from g_ss2            */
__global__ void zero_ss2(void)
{
    int i = blockIdx.x * blockDim.x + threadIdx.x;
    if (i < NROWS) g_ss2[i] = 0.f;
}
__global__ void rms_finish(void)
{
    int i = blockIdx.x * blockDim.x + threadIdx.x;
    if (i < NROWS) g_scale[i] = rsqrtf(g_ss2[i] / 512.f + 1e-12f);
}

/* LayerNorm(a + res) * g + b  -- warp per row                         */
__global__ void __launch_bounds__(256)
ln_res(const float* __restrict__ a, const float* __restrict__ res,
       const float* __restrict__ g, const float* __restrict__ bb,
       float* __restrict__ out, int rnd)
{
    int row  = blockIdx.x * 8 + (threadIdx.x >> 5);
    int lane = threadIdx.x & 31;
    const float* ar = a   + (size_t)row * 256;
    const float* rr = res + (size_t)row * 256;

    float v[8];
    float s = 0.f;
#pragma unroll
    for (int j = 0; j < 8; j++) {
        int cidx = lane + j * 32;
        v[j] = ar[cidx] + rr[cidx];
        s += v[j];
    }
#pragma unroll
    for (int o = 16; o > 0; o >>= 1) s += __shfl_xor_sync(0xffffffff, s, o);
    float mean = s * (1.f / 256.f);

    float vs = 0.f;
#pragma unroll
    for (int j = 0; j < 8; j++) {
        float d = v[j] - mean;
        vs += d * d;
    }
#pragma unroll
    for (int o = 16; o > 0; o >>= 1) vs += __shfl_xor_sync(0xffffffff, vs, o);
    float inv = rsqrtf(vs * (1.f / 256.f) + 1e-12f);

    float* orow = out + (size_t)row * 256;
#pragma unroll
    for (int j = 0; j < 8; j++) {
        int cidx = lane + j * 32;
        float o = (v[j] - mean) * inv * g[cidx] + bb[cidx];
        orow[cidx] = rnd ? tf32r(o) : o;
    }
}

/* ------------------------------------------------------------------ */
extern "C" void kernel_launch(void* const* d_in, const int* in_sizes, int n_in,
                              void* d_out, int out_size)
{
    const float* x       = (const float*)d_in[0];
    const float* in_w    = (const float*)d_in[1];
    const float* in_b    = (const float*)d_in[2];
    const float* conv_w  = (const float*)d_in[3];
    const float* conv_b  = (const float*)d_in[4];
    const float* dt_bias = (const float*)d_in[5];
    const float* A_log   = (const float*)d_in[6];
    const float* Dp      = (const float*)d_in[7];
    const float* norm_w  = (const float*)d_in[8];
    const float* out_w   = (const float*)d_in[9];
    const float* out_b   = (const float*)d_in[10];
    const float* ln_g    = (const float*)d_in[11];
    const float* ln_b    = (const float*)d_in[12];
    const float* fc1_w   = (const float*)d_in[13];
    const float* fc1_b   = (const float*)d_in[14];
    const float* fc2_w   = (const float*)d_in[15];
    const float* fc2_b   = (const float*)d_in[16];
    const float* fln_g   = (const float*)d_in[17];
    const float* fln_b   = (const float*)d_in[18];
    float* out = (float*)d_out;

    void *p;
    cudaGetSymbolAddress(&p, g_zxbcdt);  float* zx     = (float*)p;
    cudaGetSymbolAddress(&p, g_yn);      float* yn     = (float*)p;
    cudaGetSymbolAddress(&p, g_t256);    float* t256   = (float*)p;
    cudaGetSymbolAddress(&p, g_hidden);  float* hidden = (float*)p;
    cudaGetSymbolAddress(&p, g_h1);      float* h1     = (float*)p;
    cudaGetSymbolAddress(&p, g_wtf);     float* wtf    = (float*)p;
    cudaGetSymbolAddress(&p, g_scale);   float* rscale = (float*)p;

    static int chunk_smem = (4 * SZT + 128) * 4;
    static int ssdy_smem  = (4 * SZT + 256) * 4;
    cudaFuncSetAttribute(chunk_kernel,
                         cudaFuncAttributeMaxDynamicSharedMemorySize, chunk_smem);
    cudaFuncSetAttribute(ssd_y,
                         cudaFuncAttributeMaxDynamicSharedMemorySize, ssdy_smem);
    cudaFuncSetAttribute(gemm_tf32,
                         cudaFuncAttributeMaxDynamicSharedMemorySize, 110592);

    /* 0. fused weight tf32 conversion + ss2 zero */
    cvt_weights<<<(W_TOTAL + 255)/256, 256>>>(in_w, out_w, fc1_w, fc2_w, norm_w);
    zero_ss2<<<NROWS/256, 256>>>();

    /* 1. in_proj (A fragments converted inline) */
    gemm_tf32<<<dim3((DPROJ + 127) / 128, NROWS / 128), 128, 110592>>>(
        x, wtf + W_IN_OFF, in_b, zx, NULL, NROWS, DPROJ, DMODEL, 0, 1);
    /* 2-3 */
    conv_kernel<<<dim3(B_SZ * NC, CONVD / CCH), 320>>>(conv_w, conv_b);
    acs_fused<<<B_SZ * NH * NC, 64>>>(dt_bias, A_log);
    /* 5. intra-chunk (heads split across 2 blocks) */
    chunk_kernel<<<dim3(B_SZ * NC, 2), 256, chunk_smem>>>();
    /* 6. inter-chunk scan */
    scan_kernel<<<(B_SZ * NH * HD * DSTATE + 255) / 256, 256>>>();
    /* 7. Y + gate (heads split across 2 blocks) + rms finish */
    ssd_y<<<dim3(B_SZ * NC, 2), 256, ssdy_smem>>>(Dp);
    rms_finish<<<NROWS/256, 256>>>();
    /* 9. out_proj with deferred RMS row-scale */
    gemm_tf32<<<dim3(DMODEL / 128, NROWS / 128), 128, 110592>>>(
        yn, wtf + W_OUT_OFF, out_b, t256, rscale, NROWS, DMODEL, DINNER, 0, 0);
    /* 10 */
    ln_res<<<NROWS / 8, 256>>>(t256, x, ln_g, ln_b, hidden, 1);
    /* 11 */
    gemm_tf32<<<dim3(DFFN / 128, NROWS / 128), 128, 110592>>>(
        hidden, wtf + W_FC1_OFF, fc1_b, h1, NULL, NROWS, DFFN, DMODEL, 1, 0);
    /* 12 */
    gemm_tf32<<<dim3(DMODEL / 128, NROWS / 128), 128, 110592>>>(
        h1, wtf + W_FC2_OFF, fc2_b, t256, NULL, NROWS, DMODEL, DFFN, 0, 0);
    /* 13 */
    ln_res<<<NROWS / 8, 256>>>(t256, hidden, fln_g, fln_b, out, 0);
}

// round 17
// speedup vs baseline: 1.2862x; 1.0170x over previous
#include <cuda_runtime.h>
#include <math.h>
#include <stdint.h>

#define B_SZ    32
#define L_SZ    2048
#define NROWS   (B_SZ*L_SZ)      /* 65536 */
#define DMODEL  256
#define DINNER  512
#define NH      8
#define HD      64
#define DSTATE  64
#define CHUNK   64
#define NC      (L_SZ/CHUNK)     /* 32 */
#define CONVD   640
#define DPROJ   1160
#define DFFN    1024

/* ------------------------------------------------------------------ */
__device__ float g_zxbcdt[(size_t)NROWS*DPROJ];
__device__ float g_xbc[(size_t)NROWS*CONVD];
__device__ float g_dtsp[(size_t)NROWS*NH];
__device__ float g_acs[(size_t)B_SZ*NH*L_SZ];
__device__ float g_cdec[B_SZ*NH*NC];
__device__ float g_G[(size_t)B_SZ*NC*CHUNK*CHUNK];
__device__ float g_states[(size_t)B_SZ*NC*NH*HD*DSTATE];  /* [n][p] */
__device__ float g_prev[(size_t)B_SZ*NC*NH*HD*DSTATE];    /* [n][p] */
__device__ float g_yn[(size_t)NROWS*DINNER];              /* unnormalized u */
__device__ float g_ss2[(size_t)NROWS];                    /* partial sum u^2 */
__device__ float g_t256[(size_t)NROWS*DMODEL];
__device__ float g_hidden[(size_t)NROWS*DMODEL];
__device__ float g_h1[(size_t)NROWS*DFFN];

#define W_IN_OFF   0
#define W_OUT_OFF  (DPROJ*DMODEL)
#define W_FC1_OFF  (W_OUT_OFF + DMODEL*DINNER)
#define W_FC2_OFF  (W_FC1_OFF + DFFN*DMODEL)
#define W_TOTAL    (W_FC2_OFF + DMODEL*DFFN)
__device__ float g_wtf[W_TOTAL];

__device__ __forceinline__ uint32_t f2tf32(float v) {
    uint32_t r;
    asm("cvt.rna.tf32.f32 %0, %1;" : "=r"(r) : "f"(v));
    return r;
}
__device__ __forceinline__ float tf32r(float v) {
    return __uint_as_float(f2tf32(v));
}

/* single fused weight convert: in_w | out_w*norm_w | fc1_w | fc2_w    */
__global__ void cvt_weights(const float* __restrict__ in_w,
                            const float* __restrict__ out_w,
                            const float* __restrict__ fc1_w,
                            const float* __restrict__ fc2_w,
                            const float* __restrict__ nw)
{
    int i = blockIdx.x * blockDim.x + threadIdx.x;
    if (i >= W_TOTAL) return;
    float v;
    if (i < W_OUT_OFF)        v = in_w[i];
    else if (i < W_FC1_OFF) { int j = i - W_OUT_OFF; v = out_w[j] * nw[j & (DINNER-1)]; }
    else if (i < W_FC2_OFF)   v = fc1_w[i - W_FC1_OFF];
    else                      v = fc2_w[i - W_FC2_OFF];
    g_wtf[i] = tf32r(v);
}

/* ------------------------------------------------------------------ */
__device__ __forceinline__ void mma_tf32(float c[4],
    uint32_t a0, uint32_t a1, uint32_t a2, uint32_t a3,
    uint32_t b0, uint32_t b1)
{
    asm volatile(
        "mma.sync.aligned.m16n8k8.row.col.f32.tf32.tf32.f32 "
        "{%0,%1,%2,%3}, {%4,%5,%6,%7}, {%8,%9}, {%0,%1,%2,%3};"
        : "+f"(c[0]), "+f"(c[1]), "+f"(c[2]), "+f"(c[3])
        : "r"(a0), "r"(a1), "r"(a2), "r"(a3), "r"(b0), "r"(b1));
}

/* ------------------------------------------------------------------ */
/* tf32 tensor-core GEMM, 3-stage cp.async pipeline                    */
/* rowss2 != NULL: v = rsqrt(ss2[row]/512+eps)*acc + bias              */
/* ------------------------------------------------------------------ */
#define SROW 36
#define TBUF (128*SROW)

__device__ __forceinline__ void cpa16(uint32_t sdst, const float* gsrc) {
    asm volatile("cp.async.cg.shared.global [%0], [%1], 16;"
                 :: "r"(sdst), "l"(gsrc));
}
__device__ __forceinline__ void cpa16z(uint32_t sdst, const float* gsrc, int valid) {
    int sz = valid ? 16 : 0;
    asm volatile("cp.async.cg.shared.global [%0], [%1], 16, %2;"
                 :: "r"(sdst), "l"(gsrc), "r"(sz));
}

__global__ void __launch_bounds__(128, 2)
gemm_tf32(const float* __restrict__ A, const float* __restrict__ W,
          const float* __restrict__ bias, float* __restrict__ C,
          const float* __restrict__ rowss2,
          int M, int N, int K, int act, int cvtA)
{
    extern __shared__ float sm[];
    float* As = sm;
    float* Ws = sm + 3 * TBUF;
    uint32_t sAs = (uint32_t)__cvta_generic_to_shared(As);
    uint32_t sWs = (uint32_t)__cvta_generic_to_shared(Ws);

    int tid  = threadIdx.x;
    int warp = tid >> 5, lane = tid & 31;
    int wm = (warp >> 1) * 64;
    int wn = (warp & 1) * 64;
    int m0 = blockIdx.y * 128;
    int n0 = blockIdx.x * 128;
    int g  = lane >> 2;
    int tg = lane & 3;

    float acc[4][8][4];
#pragma unroll
    for (int i = 0; i < 4; i++)
#pragma unroll
        for (int j = 0; j < 8; j++)
#pragma unroll
            for (int r = 0; r < 4; r++) acc[i][j][r] = 0.f;

    int ntiles = K >> 5;

#define FILL(BUF, K0) do {                                                   \
    int _k0 = (K0);                                                          \
    _Pragma("unroll")                                                        \
    for (int i = 0; i < 8; i++) {                                            \
        int c = tid + i * 128;                                               \
        int row = c >> 3, cc = (c & 7) * 4;                                  \
        cpa16(sAs + (((BUF)*TBUF + row*SROW + cc) << 2),                     \
              A + (size_t)(m0 + row) * K + _k0 + cc);                        \
        int wr = n0 + row;                                                   \
        int wv = wr < N;                                                     \
        cpa16z(sWs + (((BUF)*TBUF + row*SROW + cc) << 2),                    \
               W + (size_t)(wv ? wr : 0) * K + _k0 + cc, wv);                \
    }                                                                        \
    asm volatile("cp.async.commit_group;");                                  \
} while (0)

    FILL(0, 0);
    if (ntiles > 1) FILL(1, 32);
    for (int kt = 0; kt < ntiles; kt++) {
        if (kt + 2 < ntiles) {
            FILL((kt + 2) % 3, (kt + 2) * 32);
            asm volatile("cp.async.wait_group 2;");
        } else if (kt + 1 < ntiles) {
            asm volatile("cp.async.wait_group 1;");
        } else {
            asm volatile("cp.async.wait_group 0;");
        }
        __syncthreads();

        int buf = kt % 3;
        const uint32_t* Ab = (const uint32_t*)(As + buf * TBUF);
        const uint32_t* Wb = (const uint32_t*)(Ws + buf * TBUF);
#pragma unroll
        for (int ks = 0; ks < 4; ks++) {
            int k0 = ks * 8;
            uint32_t af[4][4];
#pragma unroll
            for (int mt = 0; mt < 4; mt++) {
                const uint32_t* ap = Ab + (wm + mt * 16 + g) * SROW + k0 + tg;
                af[mt][0] = ap[0];
                af[mt][1] = ap[8 * SROW];
                af[mt][2] = ap[4];
                af[mt][3] = ap[8 * SROW + 4];
            }
            if (cvtA) {
#pragma unroll
                for (int mt = 0; mt < 4; mt++)
#pragma unroll
                    for (int i = 0; i < 4; i++)
                        af[mt][i] = f2tf32(__uint_as_float(af[mt][i]));
            }
            uint32_t bf[8][2];
#pragma unroll
            for (int nt = 0; nt < 8; nt++) {
                const uint32_t* bp = Wb + (wn + nt * 8 + g) * SROW + k0 + tg;
                bf[nt][0] = bp[0];
                bf[nt][1] = bp[4];
            }
#pragma unroll
            for (int mt = 0; mt < 4; mt++)
#pragma unroll
                for (int nt = 0; nt < 8; nt++)
                    mma_tf32(acc[mt][nt], af[mt][0], af[mt][1], af[mt][2],
                             af[mt][3], bf[nt][0], bf[nt][1]);
        }
        __syncthreads();
    }

#pragma unroll
    for (int mt = 0; mt < 4; mt++) {
        int r0 = m0 + wm + mt * 16 + g;
        float s0 = 1.f, s2 = 1.f;
        if (rowss2) {
            s0 = rsqrtf(rowss2[r0]     * (1.f/512.f) + 1e-12f);
            s2 = rsqrtf(rowss2[r0 + 8] * (1.f/512.f) + 1e-12f);
        }
#pragma unroll
        for (int nt = 0; nt < 8; nt++) {
            int col = n0 + wn + nt * 8 + 2 * tg;
            if (col + 1 < N) {
                float b0 = bias[col], b1 = bias[col + 1];
                float v0 = acc[mt][nt][0] * s0 + b0;
                float v1 = acc[mt][nt][1] * s0 + b1;
                float v2 = acc[mt][nt][2] * s2 + b0;
                float v3 = acc[mt][nt][3] * s2 + b1;
                if (act == 1) {
                    float t;
                    t = fminf(fmaxf(v0 + 3.f, 0.f), 6.f); v0 = tf32r(v0 * t * (1.f/6.f));
                    t = fminf(fmaxf(v1 + 3.f, 0.f), 6.f); v1 = tf32r(v1 * t * (1.f/6.f));
                    t = fminf(fmaxf(v2 + 3.f, 0.f), 6.f); v2 = tf32r(v2 * t * (1.f/6.f));
                    t = fminf(fmaxf(v3 + 3.f, 0.f), 6.f); v3 = tf32r(v3 * t * (1.f/6.f));
                }
                *(float2*)(C + (size_t)r0 * N + col)       = make_float2(v0, v1);
                *(float2*)(C + (size_t)(r0 + 8) * N + col) = make_float2(v2, v3);
            } else if (col < N) {
                float b0 = bias[col];
                float v0 = acc[mt][nt][0] * s0 + b0;
                float v2 = acc[mt][nt][2] * s2 + b0;
                if (act == 1) {
                    float t;
                    t = fminf(fmaxf(v0 + 3.f, 0.f), 6.f); v0 = tf32r(v0 * t * (1.f/6.f));
                    t = fminf(fmaxf(v2 + 3.f, 0.f), 6.f); v2 = tf32r(v2 * t * (1.f/6.f));
                }
                C[(size_t)r0 * N + col]       = v0;
                C[(size_t)(r0 + 8) * N + col] = v2;
            }
        }
    }
}

/* ------------------------------------------------------------------ */
/* Causal conv (K=4) + SiLU, register stencil (no smem)                */
/* grid (B*NC, 4); 320 threads: cg = tid%40 (4ch), lb = tid/40 (8 rows)*/
/* ------------------------------------------------------------------ */
#define CCH 160
__global__ void __launch_bounds__(320)
conv_kernel(const float* __restrict__ w, const float* __restrict__ cb)
{
    int bc = blockIdx.x;
    int ct = blockIdx.y;
    int b = bc / NC, c = bc % NC;
    int tid = threadIdx.x;
    int cg = tid % 40;
    int lb = tid / 40;
    if (lb >= 8) return;
    int ch = ct * CCH + cg * 4;
    int l0 = c * 64 + lb * 8;

    float wr[4][4];
#pragma unroll
    for (int j = 0; j < 4; j++)
#pragma unroll
        for (int k = 0; k < 4; k++)
            wr[j][k] = __ldg(&w[(ch + j) * 4 + k]);
    float4 cbv = *(const float4*)(cb + ch);

    float4 rowv[11];
#pragma unroll
    for (int r = 0; r < 11; r++) {
        int ls = l0 - 3 + r;
        rowv[r] = (ls >= c * 64 - 3 && ls >= 0)
            ? *(const float4*)(g_zxbcdt + (size_t)(b * L_SZ + ls) * DPROJ + DINNER + ch)
            : make_float4(0.f, 0.f, 0.f, 0.f);
    }

#pragma unroll
    for (int o = 0; o < 8; o++) {
        float4 acc = cbv;
#pragma unroll
        for (int k = 0; k < 4; k++) {
            float4 xv = rowv[o + k];
            acc.x += xv.x * wr[0][k];
            acc.y += xv.y * wr[1][k];
            acc.z += xv.z * wr[2][k];
            acc.w += xv.w * wr[3][k];
        }
        acc.x = acc.x / (1.f + __expf(-acc.x));
        acc.y = acc.y / (1.f + __expf(-acc.y));
        acc.z = acc.z / (1.f + __expf(-acc.z));
        acc.w = acc.w / (1.f + __expf(-acc.w));
        *(float4*)(g_xbc + (size_t)(b * L_SZ + l0 + o) * CONVD + ch) = acc;
    }
}

/* fused softplus(dt) + per-chunk cumsum + chunk decay                 */
__global__ void acs_fused(const float* __restrict__ dtb,
                          const float* __restrict__ A_log)
{
    __shared__ float sh[64];
    int id = blockIdx.x;
    int c  = id % NC;
    int bh = id / NC;
    int h  = bh % NH;
    int b  = bh / NH;
    int l  = threadIdx.x;
    int r  = b * L_SZ + c * 64 + l;

    float v = g_zxbcdt[(size_t)r * DPROJ + (DPROJ - NH) + h] + __ldg(&dtb[h]);
    float dtv = (v > 20.f) ? v : log1pf(__expf(v));
    g_dtsp[(size_t)r * NH + h] = dtv;

    float Ah = -expf(__ldg(&A_log[h]));
    sh[l] = dtv * Ah;
    __syncthreads();
    for (int off = 1; off < 64; off <<= 1) {
        float t = (l >= off) ? sh[l - off] : 0.f;
        __syncthreads();
        sh[l] += t;
        __syncthreads();
    }
    g_acs[(size_t)id * 64 + l] = sh[l];
    if (l == 63) g_cdec[id] = __expf(sh[63]);
}

/* ------------------------------------------------------------------ */
#define SR 68
#define SZT (64*SR)

__device__ __forceinline__ void mm64(const float* __restrict__ sA,
                                     const float* __restrict__ sB,
                                     int wm, int wn, int g, int tg,
                                     float acc[4][4])
{
#pragma unroll
    for (int k0 = 0; k0 < 64; k0 += 8) {
        uint32_t a0 = f2tf32(sA[(wm + g)     * SR + k0 + tg]);
        uint32_t a1 = f2tf32(sA[(wm + 8 + g) * SR + k0 + tg]);
        uint32_t a2 = f2tf32(sA[(wm + g)     * SR + k0 + 4 + tg]);
        uint32_t a3 = f2tf32(sA[(wm + 8 + g) * SR + k0 + 4 + tg]);
#pragma unroll
        for (int nt = 0; nt < 4; nt++) {
            uint32_t b0 = f2tf32(sB[(wn + nt * 8 + g) * SR + k0 + tg]);
            uint32_t b1 = f2tf32(sB[(wn + nt * 8 + g) * SR + k0 + 4 + tg]);
            mma_tf32(acc[nt], a0, a1, a2, a3, b0, b1);
        }
    }
}

/* ------------------------------------------------------------------ */
/* Chunk kernel: grid (B*NC, 2); y=0 also writes G; 4 heads per block  */
/* ------------------------------------------------------------------ */
extern __shared__ float smem[];
__global__ void __launch_bounds__(256, 3)
chunk_kernel(void)
{
    float* sB   = smem;
    float* sBt  = smem + SZT;
    float* sC   = smem + 2*SZT;
    float* sXdt = smem + 3*SZT;
    float* sDec = smem + 4*SZT;
    float* sDt  = smem + 4*SZT + 64;

    int bc = blockIdx.x;
    int hb = blockIdx.y;
    int b = bc / NC, c = bc % NC;
    int tid = threadIdx.x;
    int base = b * L_SZ + c * CHUNK;

    int warp = tid >> 5, lane = tid & 31;
    int g  = lane >> 2, tg = lane & 3;
    int wm = (warp >> 1) * 16;
    int wn = (warp & 1) * 32;

    for (int i = tid; i < 1024; i += 256) {
        int l = i >> 4, n4 = (i & 15) * 4;
        const float* row = g_xbc + (size_t)(base + l) * CONVD + DINNER;
        float4 bv = *(const float4*)(row + n4);
        *(float4*)&sB[l * SR + n4] = bv;
        sBt[(n4 + 0) * SR + l] = bv.x;
        sBt[(n4 + 1) * SR + l] = bv.y;
        sBt[(n4 + 2) * SR + l] = bv.z;
        sBt[(n4 + 3) * SR + l] = bv.w;
        if (hb == 0)
            *(float4*)&sC[l * SR + n4] = *(const float4*)(row + DSTATE + n4);
    }
    __syncthreads();

    if (hb == 0) {
        float acc[4][4];
#pragma unroll
        for (int i = 0; i < 4; i++)
#pragma unroll
            for (int j = 0; j < 4; j++) acc[i][j] = 0.f;
        mm64(sC, sB, wm, wn, g, tg, acc);
        float* gp = g_G + (size_t)bc * 4096;
#pragma unroll
        for (int nt = 0; nt < 4; nt++) {
            int cl = wn + nt * 8 + 2 * tg;
            *(float2*)(gp + (wm + g)     * 64 + cl) = make_float2(acc[nt][0], acc[nt][1]);
            *(float2*)(gp + (wm + 8 + g) * 64 + cl) = make_float2(acc[nt][2], acc[nt][3]);
        }
    }

    for (int hh = 0; hh < 4; hh++) {
        int h = hb * 4 + hh;
        __syncthreads();
        if (tid < 64) {
            sDt[tid] = g_dtsp[(size_t)(base + tid) * NH + h];
            const float* ac = g_acs + ((size_t)(b * NH + h) * NC + c) * 64;
            sDec[tid] = __expf(ac[63] - ac[tid]);
        }
        __syncthreads();

        for (int i = tid; i < 1024; i += 256) {
            int s = i >> 4, p4 = (i & 15) * 4;
            float4 xv = *(const float4*)(g_xbc + (size_t)(base + s) * CONVD + h * HD + p4);
            float sc = sDt[s] * sDec[s];
            sXdt[(p4 + 0) * SR + s] = xv.x * sc;
            sXdt[(p4 + 1) * SR + s] = xv.y * sc;
            sXdt[(p4 + 2) * SR + s] = xv.z * sc;
            sXdt[(p4 + 3) * SR + s] = xv.w * sc;
        }
        __syncthreads();

        float acc[4][4];
#pragma unroll
        for (int i = 0; i < 4; i++)
#pragma unroll
            for (int j = 0; j < 4; j++) acc[i][j] = 0.f;
        mm64(sBt, sXdt, wm, wn, g, tg, acc);
        float* sp = g_states + (((size_t)bc * NH + h) << 12);
#pragma unroll
        for (int nt = 0; nt < 4; nt++) {
            int p = wn + nt * 8 + 2 * tg;
            *(float2*)(sp + (wm + g)     * 64 + p) = make_float2(acc[nt][0], acc[nt][1]);
            *(float2*)(sp + (wm + 8 + g) * 64 + p) = make_float2(acc[nt][2], acc[nt][3]);
        }
    }
}

/* sequential inter-chunk state recurrence                              */
__global__ void scan_kernel(void)
{
    int idx = blockIdx.x * blockDim.x + threadIdx.x;
    int e = idx & 4095;
    int h = (idx >> 12) & 7;
    int b = idx >> 15;
    float carry = 0.f;
    for (int c = 0; c < NC; c++) {
        size_t off = (((size_t)(b * NC + c) * NH + h) << 12) + e;
        g_prev[off] = carry;
        carry = carry * g_cdec[(b * NH + h) * NC + c] + g_states[off];
    }
}

/* ------------------------------------------------------------------ */
/* ssd_y: grid (B*NC, 2), 4 heads per block; partial sum(u^2) -> g_ss2 */
/* ------------------------------------------------------------------ */
__global__ void __launch_bounds__(256, 3)
ssd_y(const float* __restrict__ Dp)
{
    float* sC   = smem;
    float* sG   = smem + SZT;
    float* sT   = smem + 2*SZT;
    float* sXt  = smem + 3*SZT;
    float* sE   = smem + 4*SZT;
    float* sAcs = smem + 4*SZT + 64;
    float* sDt  = smem + 4*SZT + 128;
    float* sSS  = smem + 4*SZT + 192;

    int bc = blockIdx.x;
    int hb = blockIdx.y;
    int b = bc / NC, c = bc % NC;
    int tid = threadIdx.x;
    int base = b * L_SZ + c * CHUNK;

    int warp = tid >> 5, lane = tid & 31;
    int g  = lane >> 2, tg = lane & 3;
    int wm = (warp >> 1) * 16;
    int wn = (warp & 1) * 32;
    int r0 = wm + g, r1 = wm + 8 + g;

    const float* gp = g_G + (size_t)bc * 4096;
    for (int i = tid; i < 1024; i += 256) {
        int l = i >> 4, n4 = (i & 15) * 4;
        *(float4*)&sC[l * SR + n4] =
            *(const float4*)(g_xbc + (size_t)(base + l) * CONVD + DINNER + DSTATE + n4);
        *(float4*)&sG[l * SR + n4] = *(const float4*)(gp + l * 64 + n4);
    }
    if (tid < 64) sSS[tid] = 0.f;
    __syncthreads();

    float ss0 = 0.f, ss1 = 0.f;

    for (int hh = 0; hh < 4; hh++) {
        int h = hb * 4 + hh;
        if (tid < 64) {
            const float* ac = g_acs + ((size_t)(b * NH + h) * NC + c) * 64;
            float a = ac[tid];
            sAcs[tid] = a;
            sE[tid]   = __expf(a);
            sDt[tid]  = g_dtsp[(size_t)(base + tid) * NH + h];
        }
        __syncthreads();

        for (int i = tid; i < 4096; i += 256) {
            int l = i >> 6, s = i & 63;
            sT[l * SR + s] = (s <= l)
                ? sG[l * SR + s] * __expf(sAcs[l] - sAcs[s]) * sDt[s] : 0.f;
        }
        for (int i = tid; i < 1024; i += 256) {
            int s = i >> 4, p4 = (i & 15) * 4;
            float4 xv = *(const float4*)(g_xbc + (size_t)(base + s) * CONVD + h * HD + p4);
            sXt[(p4 + 0) * SR + s] = xv.x;
            sXt[(p4 + 1) * SR + s] = xv.y;
            sXt[(p4 + 2) * SR + s] = xv.z;
            sXt[(p4 + 3) * SR + s] = xv.w;
        }
        __syncthreads();

        float accY[4][4];
#pragma unroll
        for (int i = 0; i < 4; i++)
#pragma unroll
            for (int j = 0; j < 4; j++) accY[i][j] = 0.f;
        mm64(sT, sXt, wm, wn, g, tg, accY);
        __syncthreads();

        const float* pv = g_prev + (((size_t)bc * NH + h) << 12);
        for (int i = tid; i < 1024; i += 256) {
            int n = i >> 4, p4 = (i & 15) * 4;
            float4 pvv = *(const float4*)(pv + n * 64 + p4);
            sT[(p4 + 0) * SR + n] = pvv.x;
            sT[(p4 + 1) * SR + n] = pvv.y;
            sT[(p4 + 2) * SR + n] = pvv.z;
            sT[(p4 + 3) * SR + n] = pvv.w;
        }
        __syncthreads();

        float accO[4][4];
#pragma unroll
        for (int i = 0; i < 4; i++)
#pragma unroll
            for (int j = 0; j < 4; j++) accO[i][j] = 0.f;
        mm64(sC, sT, wm, wn, g, tg, accO);

        float Dph = __ldg(&Dp[h]);
        float e0 = sE[r0], e1 = sE[r1];
#pragma unroll
        for (int nt = 0; nt < 4; nt++) {
            int p = wn + nt * 8 + 2 * tg;
            float x00 = sXt[(p + 0) * SR + r0];
            float x01 = sXt[(p + 1) * SR + r0];
            float x10 = sXt[(p + 0) * SR + r1];
            float x11 = sXt[(p + 1) * SR + r1];
            float2 z0 = *(const float2*)(g_zxbcdt + (size_t)(base + r0) * DPROJ + h * HD + p);
            float2 z1 = *(const float2*)(g_zxbcdt + (size_t)(base + r1) * DPROJ + h * HD + p);
            float y00 = accY[nt][0] + e0 * accO[nt][0] + Dph * x00;
            float y01 = accY[nt][1] + e0 * accO[nt][1] + Dph * x01;
            float y10 = accY[nt][2] + e1 * accO[nt][2] + Dph * x10;
            float y11 = accY[nt][3] + e1 * accO[nt][3] + Dph * x11;
            float u00 = y00 * (z0.x / (1.f + __expf(-z0.x)));
            float u01 = y01 * (z0.y / (1.f + __expf(-z0.y)));
            float u10 = y10 * (z1.x / (1.f + __expf(-z1.x)));
            float u11 = y11 * (z1.y / (1.f + __expf(-z1.y)));
            ss0 += u00 * u00 + u01 * u01;
            ss1 += u10 * u10 + u11 * u11;
            *(float2*)(g_yn + (size_t)(base + r0) * DINNER + h * HD + p) =
                make_float2(tf32r(u00), tf32r(u01));
            *(float2*)(g_yn + (size_t)(base + r1) * DINNER + h * HD + p) =
                make_float2(tf32r(u10), tf32r(u11));
        }
        __syncthreads();
    }

    atomicAdd(&sSS[r0], ss0);
    atomicAdd(&sSS[r1], ss1);
    __syncthreads();
    if (tid < 64)
        atomicAdd(&g_ss2[base + tid], sSS[tid]);
}

__global__ void zero_ss2(void)
{
    int i = blockIdx.x * blockDim.x + threadIdx.x;
    if (i < NROWS) g_ss2[i] = 0.f;
}

/* LayerNorm(a + res) * g + b  -- warp per row                         */
__global__ void __launch_bounds__(256)
ln_res(const float* __restrict__ a, const float* __restrict__ res,
       const float* __restrict__ g, const float* __restrict__ bb,
       float* __restrict__ out, int rnd)
{
    int row  = blockIdx.x * 8 + (threadIdx.x >> 5);
    int lane = threadIdx.x & 31;
    const float* ar = a   + (size_t)row * 256;
    const float* rr = res + (size_t)row * 256;

    float v[8];
    float s = 0.f;
#pragma unroll
    for (int j = 0; j < 8; j++) {
        int cidx = lane + j * 32;
        v[j] = ar[cidx] + rr[cidx];
        s += v[j];
    }
#pragma unroll
    for (int o = 16; o > 0; o >>= 1) s += __shfl_xor_sync(0xffffffff, s, o);
    float mean = s * (1.f / 256.f);

    float vs = 0.f;
#pragma unroll
    for (int j = 0; j < 8; j++) {
        float d = v[j] - mean;
        vs += d * d;
    }
#pragma unroll
    for (int o = 16; o > 0; o >>= 1) vs += __shfl_xor_sync(0xffffffff, vs, o);
    float inv = rsqrtf(vs * (1.f / 256.f) + 1e-12f);

    float* orow = out + (size_t)row * 256;
#pragma unroll
    for (int j = 0; j < 8; j++) {
        int cidx = lane + j * 32;
        float o = (v[j] - mean) * inv * g[cidx] + bb[cidx];
        orow[cidx] = rnd ? tf32r(o) : o;
    }
}

/* ------------------------------------------------------------------ */
extern "C" void kernel_launch(void* const* d_in, const int* in_sizes, int n_in,
                              void* d_out, int out_size)
{
    const float* x       = (const float*)d_in[0];
    const float* in_w    = (const float*)d_in[1];
    const float* in_b    = (const float*)d_in[2];
    const float* conv_w  = (const float*)d_in[3];
    const float* conv_b  = (const float*)d_in[4];
    const float* dt_bias = (const float*)d_in[5];
    const float* A_log   = (const float*)d_in[6];
    const float* Dp      = (const float*)d_in[7];
    const float* norm_w  = (const float*)d_in[8];
    const float* out_w   = (const float*)d_in[9];
    const float* out_b   = (const float*)d_in[10];
    const float* ln_g    = (const float*)d_in[11];
    const float* ln_b    = (const float*)d_in[12];
    const float* fc1_w   = (const float*)d_in[13];
    const float* fc1_b   = (const float*)d_in[14];
    const float* fc2_w   = (const float*)d_in[15];
    const float* fc2_b   = (const float*)d_in[16];
    const float* fln_g   = (const float*)d_in[17];
    const float* fln_b   = (const float*)d_in[18];
    float* out = (float*)d_out;

    void *p;
    cudaGetSymbolAddress(&p, g_zxbcdt);  float* zx     = (float*)p;
    cudaGetSymbolAddress(&p, g_yn);      float* yn     = (float*)p;
    cudaGetSymbolAddress(&p, g_t256);    float* t256   = (float*)p;
    cudaGetSymbolAddress(&p, g_hidden);  float* hidden = (float*)p;
    cudaGetSymbolAddress(&p, g_h1);      float* h1     = (float*)p;
    cudaGetSymbolAddress(&p, g_wtf);     float* wtf    = (float*)p;
    cudaGetSymbolAddress(&p, g_ss2);     float* ss2    = (float*)p;

    static int chunk_smem = (4 * SZT + 128) * 4;
    static int ssdy_smem  = (4 * SZT + 256) * 4;
    cudaFuncSetAttribute(chunk_kernel,
                         cudaFuncAttributeMaxDynamicSharedMemorySize, chunk_smem);
    cudaFuncSetAttribute(ssd_y,
                         cudaFuncAttributeMaxDynamicSharedMemorySize, ssdy_smem);
    cudaFuncSetAttribute(gemm_tf32,
                         cudaFuncAttributeMaxDynamicSharedMemorySize, 110592);

    /* 0. fused weight tf32 conversion + ss2 zero */
    cvt_weights<<<(W_TOTAL + 255)/256, 256>>>(in_w, out_w, fc1_w, fc2_w, norm_w);
    zero_ss2<<<NROWS/256, 256>>>();

    /* 1. in_proj (A fragments converted inline) */
    gemm_tf32<<<dim3((DPROJ + 127) / 128, NROWS / 128), 128, 110592>>>(
        x, wtf + W_IN_OFF, in_b, zx, NULL, NROWS, DPROJ, DMODEL, 0, 1);
    /* 2-3 */
    conv_kernel<<<dim3(B_SZ * NC, CONVD / CCH), 320>>>(conv_w, conv_b);
    acs_fused<<<B_SZ * NH * NC, 64>>>(dt_bias, A_log);
    /* 5. intra-chunk (heads split across 2 blocks) */
    chunk_kernel<<<dim3(B_SZ * NC, 2), 256, chunk_smem>>>();
    /* 6. inter-chunk scan */
    scan_kernel<<<(B_SZ * NH * HD * DSTATE + 255) / 256, 256>>>();
    /* 7. Y + gate (heads split across 2 blocks) */
    ssd_y<<<dim3(B_SZ * NC, 2), 256, ssdy_smem>>>(Dp);
    /* 9. out_proj with inline RMS (from ss2) */
    gemm_tf32<<<dim3(DMODEL / 128, NROWS / 128), 128, 110592>>>(
        yn, wtf + W_OUT_OFF, out_b, t256, ss2, NROWS, DMODEL, DINNER, 0, 0);
    /* 10 */
    ln_res<<<NROWS / 8, 256>>>(t256, x, ln_g, ln_b, hidden, 1);
    /* 11 */
    gemm_tf32<<<dim3(DFFN / 128, NROWS / 128), 128, 110592>>>(
        hidden, wtf + W_FC1_OFF, fc1_b, h1, NULL, NROWS, DFFN, DMODEL, 1, 0);
    /* 12 */
    gemm_tf32<<<dim3(DMODEL / 128, NROWS / 128), 128, 110592>>>(
        h1, wtf + W_FC2_OFF, fc2_b, t256, NULL, NROWS, DMODEL, DFFN, 0, 0);
    /* 13 */
    ln_res<<<NROWS / 8, 256>>>(t256, hidden, fln_g, fln_b, out, 0);
}